// round 1
// baseline (speedup 1.0000x reference)
#include <cuda_runtime.h>

#define NN 25000
#define NE 400000
#define HD 128
#define ED 16
#define LN_EPS 1e-5f

// ---------------- device scratch (no allocations allowed) ----------------
__device__ int   g_src[NE];
__device__ int   g_dst[NE];
__device__ int   g_is64;
__device__ float g_eA[(size_t)NE * HD];   // 204.8 MB
__device__ float g_eB[(size_t)NE * HD];   // 204.8 MB
__device__ float g_agg[(size_t)NN * HD];  // 12.8 MB
__device__ float g_x[(size_t)NN * HD];    // 12.8 MB

// ---------------- edge_index dtype probe ----------------
// jnp.int64 may silently be int32 if x64 is disabled. If int64, every odd
// 32-bit word (high half of a value in [0,25000)) is zero; if int32, odd
// words are random indices (~all nonzero). Count nonzeros in first 1024
// odd words.
__global__ void detect_kernel(const int* __restrict__ raw) {
    __shared__ int cnt;
    if (threadIdx.x == 0) cnt = 0;
    __syncthreads();
    int c = 0;
    for (int t = threadIdx.x; t < 1024; t += blockDim.x)
        if (raw[2 * t + 1] != 0) c++;
    atomicAdd(&cnt, c);
    __syncthreads();
    if (threadIdx.x == 0) g_is64 = (cnt < 16) ? 1 : 0;
}

__global__ void convert_kernel(const int* __restrict__ raw) {
    int i = blockIdx.x * blockDim.x + threadIdx.x;
    if (i >= NE) return;
    if (g_is64) {
        const long long* p = (const long long*)raw;
        g_src[i] = (int)p[i];
        g_dst[i] = (int)p[NE + i];
    } else {
        g_src[i] = raw[i];
        g_dst[i] = raw[NE + i];
    }
}

// ---------------- fused 3-layer MLP + LayerNorm (+ residual) ----------------
// 128 threads = one output channel each; R rows per CTA.
// MODE 0: emb   (in = edge_attr[row], K=16, no residual)
// MODE 1: edge  (in = [x[dst] | x[src] | e[row]], K=384, residual = e)
// MODE 2: node  (in = [x[row] | agg[row]], K=256, residual = x)

template <int K, int R>
__device__ __forceinline__ void dense(const float* __restrict__ s_src, int ld,
                                      const float* __restrict__ W, float bj,
                                      int j, float* acc) {
#pragma unroll
    for (int r = 0; r < R; r++) acc[r] = bj;
    for (int k = 0; k < K; k += 4) {
        float w0 = W[(k + 0) * HD + j];
        float w1 = W[(k + 1) * HD + j];
        float w2 = W[(k + 2) * HD + j];
        float w3 = W[(k + 3) * HD + j];
#pragma unroll
        for (int r = 0; r < R; r++) {
            const float4 v = *reinterpret_cast<const float4*>(s_src + r * ld + k);
            acc[r] = fmaf(v.x, w0, acc[r]);
            acc[r] = fmaf(v.y, w1, acc[r]);
            acc[r] = fmaf(v.z, w2, acc[r]);
            acc[r] = fmaf(v.w, w3, acc[r]);
        }
    }
}

template <int K_IN, int R, int MODE>
__global__ __launch_bounds__(128) void mlp_kernel(
    const float* __restrict__ in0, const float* __restrict__ in1,
    const float* __restrict__ W1, const float* __restrict__ b1,
    const float* __restrict__ W2, const float* __restrict__ b2,
    const float* __restrict__ W3, const float* __restrict__ b3,
    const float* __restrict__ gam, const float* __restrict__ bet,
    float* __restrict__ out, int rows) {
    __shared__ float s_in[R][K_IN];
    __shared__ float s_h[2][R][HD];
    __shared__ float s_red[2][R][4];

    const int j = threadIdx.x;  // output channel
    const int row0 = blockIdx.x * R;

    // ---- gather inputs into shared ----
#pragma unroll
    for (int r = 0; r < R; r++) {
        int row = row0 + r;
        bool ok = row < rows;
        if (MODE == 0) {
            if (j < K_IN) s_in[r][j] = ok ? in0[(size_t)row * K_IN + j] : 0.f;
        } else if (MODE == 1) {
            int d = ok ? g_dst[row] : 0;
            int s = ok ? g_src[row] : 0;
            s_in[r][j]          = ok ? in0[(size_t)d * HD + j] : 0.f;
            s_in[r][HD + j]     = ok ? in0[(size_t)s * HD + j] : 0.f;
            s_in[r][2 * HD + j] = ok ? in1[(size_t)row * HD + j] : 0.f;
        } else {
            s_in[r][j]      = ok ? in0[(size_t)row * HD + j] : 0.f;
            s_in[r][HD + j] = ok ? in1[(size_t)row * HD + j] : 0.f;
        }
    }
    __syncthreads();

    float acc[R];

    // ---- layer 1: K_IN -> 128, SiLU ----
    dense<K_IN, R>(&s_in[0][0], K_IN, W1, b1[j], j, acc);
#pragma unroll
    for (int r = 0; r < R; r++) {
        float a = acc[r];
        s_h[0][r][j] = a / (1.f + __expf(-a));
    }
    __syncthreads();

    // ---- layer 2: 128 -> 128, SiLU ----
    dense<HD, R>(&s_h[0][0][0], HD, W2, b2[j], j, acc);
#pragma unroll
    for (int r = 0; r < R; r++) {
        float a = acc[r];
        s_h[1][r][j] = a / (1.f + __expf(-a));
    }
    __syncthreads();

    // ---- layer 3: 128 -> 128, then LayerNorm (+ residual) ----
    dense<HD, R>(&s_h[1][0][0], HD, W3, b3[j], j, acc);

#pragma unroll
    for (int r = 0; r < R; r++) {
        float sum = acc[r];
        float sq = acc[r] * acc[r];
#pragma unroll
        for (int o = 16; o > 0; o >>= 1) {
            sum += __shfl_xor_sync(0xffffffffu, sum, o);
            sq  += __shfl_xor_sync(0xffffffffu, sq, o);
        }
        if ((j & 31) == 0) {
            s_red[0][r][j >> 5] = sum;
            s_red[1][r][j >> 5] = sq;
        }
    }
    __syncthreads();

    float gj = gam[j], bej = bet[j];
#pragma unroll
    for (int r = 0; r < R; r++) {
        int row = row0 + r;
        if (row >= rows) continue;
        float sum = s_red[0][r][0] + s_red[0][r][1] + s_red[0][r][2] + s_red[0][r][3];
        float sq  = s_red[1][r][0] + s_red[1][r][1] + s_red[1][r][2] + s_red[1][r][3];
        float mu  = sum * (1.f / HD);
        float var = sq * (1.f / HD) - mu * mu;
        float y = (acc[r] - mu) * rsqrtf(var + LN_EPS) * gj + bej;
        if (MODE == 1) y += s_in[r][2 * HD + j];
        else if (MODE == 2) y += s_in[r][j];
        out[(size_t)row * HD + j] = y;
    }
}

// ---------------- aggregation ----------------
__global__ void zero_agg_kernel() {
    size_t i = (size_t)blockIdx.x * blockDim.x + threadIdx.x;
    if (i < (size_t)NN * HD) g_agg[i] = 0.f;
}

__global__ void scatter_kernel(const float* __restrict__ e) {
    size_t i = (size_t)blockIdx.x * blockDim.x + threadIdx.x;
    if (i >= (size_t)NE * HD) return;
    int edge = (int)(i >> 7);
    int c = (int)(i & 127);
    atomicAdd(&g_agg[(size_t)g_dst[edge] * HD + c], e[i]);
}

// ---------------- launch ----------------
extern "C" void kernel_launch(void* const* d_in, const int* in_sizes, int n_in,
                              void* d_out, int out_size) {
    const float* x_in    = (const float*)d_in[0];
    const int*   eidx    = (const int*)d_in[1];
    const float* eattr   = (const float*)d_in[2];
    const float* emb_W1  = (const float*)d_in[3];
    const float* emb_b1  = (const float*)d_in[4];
    const float* emb_W2  = (const float*)d_in[5];
    const float* emb_b2  = (const float*)d_in[6];
    const float* emb_W3  = (const float*)d_in[7];
    const float* emb_b3  = (const float*)d_in[8];
    const float* emb_g   = (const float*)d_in[9];
    const float* emb_be  = (const float*)d_in[10];
    const float* edge_W1 = (const float*)d_in[11];
    const float* edge_b1 = (const float*)d_in[12];
    const float* edge_W2 = (const float*)d_in[13];
    const float* edge_b2 = (const float*)d_in[14];
    const float* edge_W3 = (const float*)d_in[15];
    const float* edge_b3 = (const float*)d_in[16];
    const float* edge_g  = (const float*)d_in[17];
    const float* edge_be = (const float*)d_in[18];
    const float* node_W1 = (const float*)d_in[19];
    const float* node_b1 = (const float*)d_in[20];
    const float* node_W2 = (const float*)d_in[21];
    const float* node_b2 = (const float*)d_in[22];
    const float* node_W3 = (const float*)d_in[23];
    const float* node_b3 = (const float*)d_in[24];
    const float* node_g  = (const float*)d_in[25];
    const float* node_be = (const float*)d_in[26];

    float* out_x = (float*)d_out;
    float* out_e = (float*)d_out + (size_t)NN * HD;

    float *eA, *eB, *agg, *xbuf;
    cudaGetSymbolAddress((void**)&eA, g_eA);
    cudaGetSymbolAddress((void**)&eB, g_eB);
    cudaGetSymbolAddress((void**)&agg, g_agg);
    cudaGetSymbolAddress((void**)&xbuf, g_x);

    constexpr int R = 16;
    const int edge_blocks = NE / R;            // 25000
    const int node_blocks = (NN + R - 1) / R;  // 1563
    const int zero_blocks = (NN * HD + 255) / 256;
    const int scat_blocks = (int)(((size_t)NE * HD + 255) / 256);

    // index dtype probe + normalize to int32
    detect_kernel<<<1, 256>>>(eidx);
    convert_kernel<<<(NE + 255) / 256, 256>>>(eidx);

    // edge embedding: e = MLP(edge_attr)
    mlp_kernel<ED, R, 0><<<edge_blocks, 128>>>(
        eattr, nullptr, emb_W1, emb_b1, emb_W2, emb_b2, emb_W3, emb_b3,
        emb_g, emb_be, eA, NE);

    const float* x_cur = x_in;
    float* e_cur = eA;

    for (int l = 0; l < 2; l++) {
        const float* eW1 = edge_W1 + (size_t)l * 3 * HD * HD;
        const float* eW2 = edge_W2 + (size_t)l * HD * HD;
        const float* eW3 = edge_W3 + (size_t)l * HD * HD;
        const float* nW1 = node_W1 + (size_t)l * 2 * HD * HD;
        const float* nW2 = node_W2 + (size_t)l * HD * HD;
        const float* nW3 = node_W3 + (size_t)l * HD * HD;
        const float* eb1 = edge_b1 + l * HD, *eb2 = edge_b2 + l * HD;
        const float* eb3 = edge_b3 + l * HD, *eg = edge_g + l * HD, *ebe = edge_be + l * HD;
        const float* nb1 = node_b1 + l * HD, *nb2 = node_b2 + l * HD;
        const float* nb3 = node_b3 + l * HD, *ng = node_g + l * HD, *nbe = node_be + l * HD;

        float* e_out = (l == 0) ? eB : out_e;
        float* x_out = (l == 0) ? xbuf : out_x;

        // e_new = MLP([x[dst]|x[src]|e]) + e
        mlp_kernel<3 * HD, R, 1><<<edge_blocks, 128>>>(
            x_cur, e_cur, eW1, eb1, eW2, eb2, eW3, eb3, eg, ebe, e_out, NE);

        // agg = segment_sum(e_new, dst)
        zero_agg_kernel<<<zero_blocks, 256>>>();
        scatter_kernel<<<scat_blocks, 256>>>(e_out);

        // x = MLP([x|agg]) + x
        mlp_kernel<2 * HD, R, 2><<<node_blocks, 128>>>(
            x_cur, agg, nW1, nb1, nW2, nb2, nW3, nb3, ng, nbe, x_out, NN);

        e_cur = e_out;
        x_cur = x_out;
    }
}

// round 7
// speedup vs baseline: 1.8107x; 1.8107x over previous
#include <cuda_runtime.h>
#include <cuda_fp16.h>
#include <cstdint>

#define NN 25000
#define NE 400000
#define HD 128
#define LN_EPS 1e-5f

// ================= device scratch =================
__device__ int   g_src[NE];
__device__ int   g_dst[NE];
__device__ int   g_is64;
__device__ float g_eA[(size_t)NE * HD];
__device__ float g_eB[(size_t)NE * HD];
__device__ float g_agg[(size_t)NN * HD];
__device__ float g_x[(size_t)NN * HD];

// fp16 hi/lo weight pools, [n=128][Kpad] row-major per matrix
#define POOL_ELEMS 335872
__device__ __align__(16) __half g_wh[POOL_ELEMS];
__device__ __align__(16) __half g_wl[POOL_ELEMS];

// ================= smem layout (dynamic, bytes) =================
// All tiles: 128 rows x 64 k halves, row stride 144 bytes (64*2 + 16 pad).
#define SW_HI    0u
#define SW_LO    18432u
#define SA_HI    36864u
#define SA_LO    55296u
#define HA0_HI   73728u
#define HA0_LO   92160u
#define HA1_HI   110592u
#define HA1_LO   129024u
#define HB0_HI   147456u
#define HB0_LO   165888u
#define HB1_HI   184320u
#define HB1_LO   202752u
#define SMEM_DYN 221184
#define LDT      144u
// f32 out staging overlays [0, 66560) = W + A regions (consumed by then)

// ================= helpers =================
__device__ __forceinline__ uint32_t smem_u32(const void* p) {
    uint32_t a;
    asm("{ .reg .u64 t; cvta.to.shared.u64 t, %1; cvt.u32.u64 %0, t; }"
        : "=r"(a) : "l"(p));
    return a;
}
__device__ __forceinline__ void ldsm4(uint32_t addr, uint32_t* r) {
    asm volatile("ldmatrix.sync.aligned.m8n8.x4.shared.b16 {%0,%1,%2,%3}, [%4];"
                 : "=r"(r[0]), "=r"(r[1]), "=r"(r[2]), "=r"(r[3]) : "r"(addr));
}
__device__ __forceinline__ void mma16816(float* d, const uint32_t* a,
                                         uint32_t b0, uint32_t b1) {
    asm volatile(
        "mma.sync.aligned.m16n8k16.row.col.f32.f16.f16.f32 "
        "{%0,%1,%2,%3}, {%4,%5,%6,%7}, {%8,%9}, {%0,%1,%2,%3};"
        : "+f"(d[0]), "+f"(d[1]), "+f"(d[2]), "+f"(d[3])
        : "r"(a[0]), "r"(a[1]), "r"(a[2]), "r"(a[3]), "r"(b0), "r"(b1));
}
__device__ __forceinline__ void pack_pair(float a, float b, uint32_t& hi, uint32_t& lo) {
    __half ha = __float2half_rn(a), hb = __float2half_rn(b);
    float ra = a - __half2float(ha);
    float rb = b - __half2float(hb);
    __half2 H = __halves2half2(ha, hb);
    __half2 L = __floats2half2_rn(ra, rb);
    hi = *reinterpret_cast<uint32_t*>(&H);
    lo = *reinterpret_cast<uint32_t*>(&L);
}
__device__ __forceinline__ float silu(float v) { return v / (1.f + __expf(-v)); }

// ================= index prep =================
__global__ void detect_kernel(const int* __restrict__ raw) {
    __shared__ int cnt;
    if (threadIdx.x == 0) cnt = 0;
    __syncthreads();
    int c = 0;
    for (int t = threadIdx.x; t < 1024; t += blockDim.x)
        if (raw[2 * t + 1] != 0) c++;
    atomicAdd(&cnt, c);
    __syncthreads();
    if (threadIdx.x == 0) g_is64 = (cnt < 16) ? 1 : 0;
}
// clamp indices so every later gather/scatter is in-bounds by construction
__global__ void convert_kernel(const int* __restrict__ raw) {
    int i = blockIdx.x * blockDim.x + threadIdx.x;
    if (i >= NE) return;
    int s, d;
    if (g_is64) {
        const long long* p = (const long long*)raw;
        s = (int)p[i];
        d = (int)p[NE + i];
    } else {
        s = raw[i];
        d = raw[NE + i];
    }
    if ((unsigned)s >= NN) s = 0;
    if ((unsigned)d >= NN) d = 0;
    g_src[i] = s;
    g_dst[i] = d;
}

// ================= weight split prep =================
#define NJOBS 15
struct WJob { const float* src; int Ksrc; int Kpad; int dst; };
struct WJobs { WJob j[NJOBS]; };
__global__ void conv_w_kernel(WJobs jobs) {
    WJob jb = jobs.j[blockIdx.y];
    int idx = blockIdx.x * 256 + threadIdx.x;
    if (idx >= 128 * jb.Kpad) return;
    int n = idx / jb.Kpad, k = idx % jb.Kpad;
    float v = (k < jb.Ksrc) ? jb.src[(size_t)k * 128 + n] : 0.f;
    __half h = __float2half_rn(v);
    float r = v - __half2float(h);
    g_wh[(size_t)jb.dst + (size_t)n * jb.Kpad + k] = h;
    g_wl[(size_t)jb.dst + (size_t)n * jb.Kpad + k] = __float2half_rn(r);
}

// ================= tile fill (fused gather) =================
// A tile [128 rows][64 k] fp16 hi/lo, padded rows: off = r*144 + k*2
template <int MODE>
__device__ __forceinline__ void fill_a(char* sm, const float* __restrict__ in0,
                                       const float* __restrict__ in1,
                                       int chunk, int row0, int rows) {
    const int t = threadIdx.x;            // 256 threads
    const int r = t >> 1;                 // 0..127
    const int kh = (t & 1) << 5;          // local k base: 0 or 32
    const int gk = chunk * 64 + kh;       // global k for this 32-col span
    const int row = row0 + r;
    const float* src = nullptr;
    if (MODE == 0) {
        if (kh == 0 && row < rows) src = in0 + (size_t)row * 16;
    } else if (MODE == 1) {
        if (row < rows) {
            int sect = gk >> 7;            // 0: x[dst], 1: x[src], 2: e
            int coff = gk & 127;
            if (sect == 0)      src = in0 + (size_t)g_dst[row] * HD + coff;
            else if (sect == 1) src = in0 + (size_t)g_src[row] * HD + coff;
            else                src = in1 + (size_t)row * HD + coff;
        }
    } else {
        if (row < rows) {
            int sect = gk >> 7;            // 0: x, 1: agg
            int coff = gk & 127;
            src = (sect ? in1 : in0) + (size_t)row * HD + coff;
        }
    }
    const uint32_t rbase = (uint32_t)r * LDT;
#pragma unroll
    for (int g = 0; g < 4; g++) {
        float4 v0 = make_float4(0.f, 0.f, 0.f, 0.f), v1 = v0;
        bool have = (src != nullptr) && !(MODE == 0 && g >= 2);
        if (have) {
            v0 = *(const float4*)(src + g * 8);
            v1 = *(const float4*)(src + g * 8 + 4);
        }
        uint32_t h[4], l[4];
        pack_pair(v0.x, v0.y, h[0], l[0]);
        pack_pair(v0.z, v0.w, h[1], l[1]);
        pack_pair(v1.x, v1.y, h[2], l[2]);
        pack_pair(v1.z, v1.w, h[3], l[3]);
        uint32_t off = rbase + (uint32_t)(kh + g * 8) * 2u;
        *(uint4*)(sm + SA_HI + off) = make_uint4(h[0], h[1], h[2], h[3]);
        *(uint4*)(sm + SA_LO + off) = make_uint4(l[0], l[1], l[2], l[3]);
    }
}

// W tile [128 n][64 k] from pools (padded rows)
__device__ __forceinline__ void load_w(char* sm, int wofs, int kc, int Kpad) {
    const int t = threadIdx.x;
    const int n = t >> 1;
    const int kh = (t & 1) << 5;
    const __half* ph = g_wh + wofs + (size_t)n * Kpad + kc + kh;
    const __half* pl = g_wl + wofs + (size_t)n * Kpad + kc + kh;
    const uint32_t nb = (uint32_t)n * LDT;
#pragma unroll
    for (int g = 0; g < 4; g++) {
        uint4 vh = *(const uint4*)(ph + g * 8);
        uint4 vl = *(const uint4*)(pl + g * 8);
        uint32_t off = nb + (uint32_t)(kh + g * 8) * 2u;
        *(uint4*)(sm + SW_HI + off) = vh;
        *(uint4*)(sm + SW_LO + off) = vl;
    }
}

// ================= warp MMA over one 64-k chunk =================
__device__ __forceinline__ void mma_chunk(uint32_t sb, uint32_t aHi, uint32_t aLo,
                                          float (&acc)[2][8][4], int m0, int n0, int lane) {
    const int rowA = m0 + (lane & 15);
    const int kselA = (lane >> 4) << 3;
    const uint32_t aB0 = (uint32_t)rowA * LDT;
    const uint32_t aB1 = aB0 + 16u * LDT;
    const int rowB = n0 + (lane & 7) + (((lane >> 4) & 1) << 3);
    const int kselB = ((lane >> 3) & 1) << 3;
#pragma unroll
    for (int k16 = 0; k16 < 64; k16 += 16) {
        uint32_t ah[2][4], al[2][4], bh[4][4], bl[4][4];
        uint32_t ak = (uint32_t)(k16 + kselA) * 2u;
        ldsm4(sb + aHi + aB0 + ak, ah[0]);
        ldsm4(sb + aHi + aB1 + ak, ah[1]);
        ldsm4(sb + aLo + aB0 + ak, al[0]);
        ldsm4(sb + aLo + aB1 + ak, al[1]);
        uint32_t bk = (uint32_t)(k16 + kselB) * 2u;
#pragma unroll
        for (int nb = 0; nb < 4; nb++) {
            uint32_t bb = (uint32_t)(rowB + nb * 16) * LDT;
            ldsm4(sb + SW_HI + bb + bk, bh[nb]);
            ldsm4(sb + SW_LO + bb + bk, bl[nb]);
        }
#pragma unroll
        for (int mi = 0; mi < 2; mi++)
#pragma unroll
            for (int nb = 0; nb < 4; nb++) {
                mma16816(acc[mi][nb * 2],     ah[mi], bh[nb][0], bh[nb][1]);
                mma16816(acc[mi][nb * 2 + 1], ah[mi], bh[nb][2], bh[nb][3]);
                mma16816(acc[mi][nb * 2],     al[mi], bh[nb][0], bh[nb][1]);
                mma16816(acc[mi][nb * 2 + 1], al[mi], bh[nb][2], bh[nb][3]);
                mma16816(acc[mi][nb * 2],     ah[mi], bl[nb][0], bl[nb][1]);
                mma16816(acc[mi][nb * 2 + 1], ah[mi], bl[nb][2], bl[nb][3]);
            }
    }
}

// ================= epilogues =================
__device__ __forceinline__ void epi_silu(char* sm, float (&acc)[2][8][4],
                                         const float* bias, int m0, int n0, int lane,
                                         uint32_t h0Hi, uint32_t h0Lo,
                                         uint32_t h1Hi, uint32_t h1Lo) {
    const int cq = (lane & 3) << 1;
    const int r0l = lane >> 2;
#pragma unroll
    for (int mi = 0; mi < 2; mi++)
#pragma unroll
        for (int j = 0; j < 8; j++) {
            int c = n0 + j * 8 + cq;
            float b0 = bias[c], b1 = bias[c + 1];
            uint32_t hiT = (c < 64) ? h0Hi : h1Hi;
            uint32_t loT = (c < 64) ? h0Lo : h1Lo;
            int hc = c & 63;
#pragma unroll
            for (int h = 0; h < 2; h++) {
                float v0 = silu(acc[mi][j][2 * h] + b0);
                float v1 = silu(acc[mi][j][2 * h + 1] + b1);
                uint32_t hi, lo;
                pack_pair(v0, v1, hi, lo);
                int r = m0 + mi * 16 + r0l + 8 * h;
                uint32_t off = (uint32_t)r * LDT + (uint32_t)(hc * 2);
                *(uint32_t*)(sm + hiT + off) = hi;
                *(uint32_t*)(sm + loT + off) = lo;
            }
        }
}

__device__ __forceinline__ void epi_ln(char* sm, float (&acc)[2][8][4],
                                       const float* bias, const float* gam,
                                       const float* bet,
                                       float (*sRed)[128][2],
                                       int m0, int n0, int wn, int lane) {
    const int cq = (lane & 3) << 1;
    const int r0l = lane >> 2;
    float s[2][2] = {{0.f, 0.f}, {0.f, 0.f}};
    float q[2][2] = {{0.f, 0.f}, {0.f, 0.f}};
#pragma unroll
    for (int mi = 0; mi < 2; mi++)
#pragma unroll
        for (int j = 0; j < 8; j++) {
            int c = n0 + j * 8 + cq;
            float b0 = bias[c], b1 = bias[c + 1];
#pragma unroll
            for (int h = 0; h < 2; h++) {
                float v0 = acc[mi][j][2 * h] + b0;
                float v1 = acc[mi][j][2 * h + 1] + b1;
                s[mi][h] += v0 + v1;
                q[mi][h] += v0 * v0 + v1 * v1;
            }
        }
#pragma unroll
    for (int o = 1; o <= 2; o <<= 1)
#pragma unroll
        for (int mi = 0; mi < 2; mi++)
#pragma unroll
            for (int h = 0; h < 2; h++) {
                s[mi][h] += __shfl_xor_sync(0xffffffffu, s[mi][h], o);
                q[mi][h] += __shfl_xor_sync(0xffffffffu, q[mi][h], o);
            }
    if ((lane & 3) == 0) {
#pragma unroll
        for (int mi = 0; mi < 2; mi++)
#pragma unroll
            for (int h = 0; h < 2; h++) {
                int r = m0 + mi * 16 + r0l + 8 * h;
                sRed[wn][r][0] = s[mi][h];
                sRed[wn][r][1] = q[mi][h];
            }
    }
    __syncthreads();
    float mu[2][2], rs[2][2];
#pragma unroll
    for (int mi = 0; mi < 2; mi++)
#pragma unroll
        for (int h = 0; h < 2; h++) {
            int r = m0 + mi * 16 + r0l + 8 * h;
            float S = sRed[0][r][0] + sRed[1][r][0];
            float Q = sRed[0][r][1] + sRed[1][r][1];
            float m = S * (1.f / HD);
            float var = Q * (1.f / HD) - m * m;
            mu[mi][h] = m;
            rs[mi][h] = rsqrtf(var + LN_EPS);
        }
    float* so = (float*)sm;  // stride 130 floats, region [0, 66560)
#pragma unroll
    for (int mi = 0; mi < 2; mi++)
#pragma unroll
        for (int j = 0; j < 8; j++) {
            int c = n0 + j * 8 + cq;
            float b0 = bias[c], b1 = bias[c + 1];
            float g0 = gam[c], g1 = gam[c + 1];
            float e0 = bet[c], e1 = bet[c + 1];
#pragma unroll
            for (int h = 0; h < 2; h++) {
                int r = m0 + mi * 16 + r0l + 8 * h;
                float v0 = acc[mi][j][2 * h] + b0;
                float v1 = acc[mi][j][2 * h + 1] + b1;
                so[r * 130 + c]     = (v0 - mu[mi][h]) * rs[mi][h] * g0 + e0;
                so[r * 130 + c + 1] = (v1 - mu[mi][h]) * rs[mi][h] * g1 + e1;
            }
        }
}

// ================= fused MLP kernel =================
template <int MODE, int NCH>
__global__ __launch_bounds__(256, 1) void mma_mlp(
    const float* __restrict__ in0, const float* __restrict__ in1,
    int o1, int o2, int o3, int Kpad1,
    const float* __restrict__ b1, const float* __restrict__ b2,
    const float* __restrict__ b3, const float* __restrict__ gam,
    const float* __restrict__ bet,
    const float* __restrict__ resid, float* __restrict__ out, int rows) {
    extern __shared__ char sm[];
    __shared__ float sP[5][HD];
    __shared__ float sRed[2][128][2];
    const int t = threadIdx.x;
    if (t < HD) {
        sP[0][t] = b1[t]; sP[1][t] = b2[t]; sP[2][t] = b3[t];
        sP[3][t] = gam[t]; sP[4][t] = bet[t];
    }
    const uint32_t sb = smem_u32(sm);
    const int lane = t & 31, w = t >> 5;
    const int m0 = (w & 3) * 32, n0 = (w >> 2) * 64, wn = w >> 2;
    const int row0 = blockIdx.x * 128;
    float acc[2][8][4];

    // ---- layer 1: K = NCH*64 -> 128, SiLU -> HA tiles ----
#pragma unroll
    for (int mi = 0; mi < 2; mi++)
        for (int j = 0; j < 8; j++)
            for (int e = 0; e < 4; e++) acc[mi][j][e] = 0.f;
    for (int c = 0; c < NCH; c++) {
        __syncthreads();
        fill_a<MODE>(sm, in0, in1, c, row0, rows);
        load_w(sm, o1, c * 64, Kpad1);
        __syncthreads();
        mma_chunk(sb, SA_HI, SA_LO, acc, m0, n0, lane);
    }
    __syncthreads();
    epi_silu(sm, acc, sP[0], m0, n0, lane, HA0_HI, HA0_LO, HA1_HI, HA1_LO);

    // ---- layer 2: 128 -> 128, SiLU -> HB tiles ----
#pragma unroll
    for (int mi = 0; mi < 2; mi++)
        for (int j = 0; j < 8; j++)
            for (int e = 0; e < 4; e++) acc[mi][j][e] = 0.f;
    for (int c = 0; c < 2; c++) {
        __syncthreads();
        load_w(sm, o2, c * 64, 128);
        __syncthreads();
        mma_chunk(sb, c ? HA1_HI : HA0_HI, c ? HA1_LO : HA0_LO, acc, m0, n0, lane);
    }
    __syncthreads();
    epi_silu(sm, acc, sP[1], m0, n0, lane, HB0_HI, HB0_LO, HB1_HI, HB1_LO);

    // ---- layer 3: 128 -> 128, LayerNorm ----
#pragma unroll
    for (int mi = 0; mi < 2; mi++)
        for (int j = 0; j < 8; j++)
            for (int e = 0; e < 4; e++) acc[mi][j][e] = 0.f;
    for (int c = 0; c < 2; c++) {
        __syncthreads();
        load_w(sm, o3, c * 64, 128);
        __syncthreads();
        mma_chunk(sb, c ? HB1_HI : HB0_HI, c ? HB1_LO : HB0_LO, acc, m0, n0, lane);
    }
    __syncthreads();
    epi_ln(sm, acc, sP[2], sP[3], sP[4], sRed, m0, n0, wn, lane);
    __syncthreads();

    // ---- residual + coalesced store ----
    const float* so = (const float*)sm;
    const int col = t & 127;
    for (int r = (t >> 7); r < 128; r += 2) {
        int row = row0 + r;
        if (row < rows) {
            float y = so[r * 130 + col];
            if (MODE != 0) y += resid[(size_t)row * HD + col];
            out[(size_t)row * HD + col] = y;
        }
    }
}

// ================= aggregation =================
__global__ void zero_agg_kernel() {
    size_t i = (size_t)blockIdx.x * blockDim.x + threadIdx.x;
    if (i < (size_t)NN * HD) g_agg[i] = 0.f;
}
__global__ void scatter_kernel(const float* __restrict__ e) {
    size_t i = (size_t)blockIdx.x * blockDim.x + threadIdx.x;
    if (i >= (size_t)NE * HD) return;
    int edge = (int)(i >> 7);
    int c = (int)(i & 127);
    atomicAdd(&g_agg[(size_t)g_dst[edge] * HD + c], e[i]);
}

// ================= launch =================
extern "C" void kernel_launch(void* const* d_in, const int* in_sizes, int n_in,
                              void* d_out, int out_size) {
    const float* x_in    = (const float*)d_in[0];
    const int*   eidx    = (const int*)d_in[1];
    const float* eattr   = (const float*)d_in[2];
    const float* emb_W1  = (const float*)d_in[3];
    const float* emb_b1  = (const float*)d_in[4];
    const float* emb_W2  = (const float*)d_in[5];
    const float* emb_b2  = (const float*)d_in[6];
    const float* emb_W3  = (const float*)d_in[7];
    const float* emb_b3  = (const float*)d_in[8];
    const float* emb_g   = (const float*)d_in[9];
    const float* emb_be  = (const float*)d_in[10];
    const float* edge_W1 = (const float*)d_in[11];
    const float* edge_b1 = (const float*)d_in[12];
    const float* edge_W2 = (const float*)d_in[13];
    const float* edge_b2 = (const float*)d_in[14];
    const float* edge_W3 = (const float*)d_in[15];
    const float* edge_b3 = (const float*)d_in[16];
    const float* edge_g  = (const float*)d_in[17];
    const float* edge_be = (const float*)d_in[18];
    const float* node_W1 = (const float*)d_in[19];
    const float* node_b1 = (const float*)d_in[20];
    const float* node_W2 = (const float*)d_in[21];
    const float* node_b2 = (const float*)d_in[22];
    const float* node_W3 = (const float*)d_in[23];
    const float* node_b3 = (const float*)d_in[24];
    const float* node_g  = (const float*)d_in[25];
    const float* node_be = (const float*)d_in[26];

    float* out_x = (float*)d_out;
    float* out_e = (float*)d_out + (size_t)NN * HD;

    float *eA, *eB, *agg, *xbuf;
    cudaGetSymbolAddress((void**)&eA, g_eA);
    cudaGetSymbolAddress((void**)&eB, g_eB);
    cudaGetSymbolAddress((void**)&agg, g_agg);
    cudaGetSymbolAddress((void**)&xbuf, g_x);

    cudaFuncSetAttribute(mma_mlp<0, 1>, cudaFuncAttributeMaxDynamicSharedMemorySize, SMEM_DYN);
    cudaFuncSetAttribute(mma_mlp<1, 6>, cudaFuncAttributeMaxDynamicSharedMemorySize, SMEM_DYN);
    cudaFuncSetAttribute(mma_mlp<2, 4>, cudaFuncAttributeMaxDynamicSharedMemorySize, SMEM_DYN);

    // index prep (clamped)
    detect_kernel<<<1, 256>>>(eidx);
    convert_kernel<<<(NE + 255) / 256, 256>>>(eidx);

    // pool offsets (elements)
    const int oEmb1 = 0, oEmb2 = 8192, oEmb3 = 24576;
    int oE1[2], oE2[2], oE3[2], oN1[2], oN2[2], oN3[2];
    int base = 40960;
    for (int l = 0; l < 2; l++) {
        oE1[l] = base;
        oE2[l] = base + 49152;
        oE3[l] = base + 65536;
        oN1[l] = base + 81920;
        oN2[l] = base + 114688;
        oN3[l] = base + 131072;
        base += 147456;
    }

    // EXACTLY NJOBS jobs; grid.y == NJOBS (bug in R3-R6 was y=21 with 15 filled)
    WJobs jobs;
    int ji = 0;
    jobs.j[ji++] = {emb_W1, 16, 64, oEmb1};
    jobs.j[ji++] = {emb_W2, 128, 128, oEmb2};
    jobs.j[ji++] = {emb_W3, 128, 128, oEmb3};
    for (int l = 0; l < 2; l++) {
        jobs.j[ji++] = {edge_W1 + (size_t)l * 3 * HD * HD, 384, 384, oE1[l]};
        jobs.j[ji++] = {edge_W2 + (size_t)l * HD * HD, 128, 128, oE2[l]};
        jobs.j[ji++] = {edge_W3 + (size_t)l * HD * HD, 128, 128, oE3[l]};
        jobs.j[ji++] = {node_W1 + (size_t)l * 2 * HD * HD, 256, 256, oN1[l]};
        jobs.j[ji++] = {node_W2 + (size_t)l * HD * HD, 128, 128, oN2[l]};
        jobs.j[ji++] = {node_W3 + (size_t)l * HD * HD, 128, 128, oN3[l]};
    }
    dim3 cg((128 * 384 + 255) / 256, NJOBS);
    conv_w_kernel<<<cg, 256>>>(jobs);

    const int edge_blocks = NE / 128;           // 3125
    const int node_blocks = (NN + 127) / 128;   // 196
    const int ethr_blocks = (int)(((size_t)NE * HD + 255) / 256);
    const int nthr_blocks = (int)(((size_t)NN * HD + 255) / 256);

    // edge embedding: e = MLP(edge_attr)
    mma_mlp<0, 1><<<edge_blocks, 256, SMEM_DYN>>>(
        eattr, nullptr, oEmb1, oEmb2, oEmb3, 64,
        emb_b1, emb_b2, emb_b3, emb_g, emb_be, nullptr, eA, NE);

    const float* x_cur = x_in;
    float* e_cur = eA;
    for (int l = 0; l < 2; l++) {
        float* e_out = (l == 0) ? eB : out_e;
        float* x_out = (l == 0) ? xbuf : out_x;

        // e_new = MLP([x[dst] | x[src] | e]) + e
        mma_mlp<1, 6><<<edge_blocks, 256, SMEM_DYN>>>(
            x_cur, e_cur, oE1[l], oE2[l], oE3[l], 384,
            edge_b1 + l * HD, edge_b2 + l * HD, edge_b3 + l * HD,
            edge_g + l * HD, edge_be + l * HD, e_cur, e_out, NE);

        // agg = segment_sum(e_new, dst)
        zero_agg_kernel<<<nthr_blocks, 256>>>();
        scatter_kernel<<<ethr_blocks, 256>>>(e_out);

        // x = MLP([x | agg]) + x
        mma_mlp<2, 4><<<node_blocks, 256, SMEM_DYN>>>(
            x_cur, agg, oN1[l], oN2[l], oN3[l], 256,
            node_b1 + l * HD, node_b2 + l * HD, node_b3 + l * HD,
            node_g + l * HD, node_be + l * HD, x_cur, x_out, NN);

        e_cur = e_out;
        x_cur = x_out;
    }
}

// round 8
// speedup vs baseline: 2.4717x; 1.3651x over previous
#include <cuda_runtime.h>
#include <cuda_fp16.h>
#include <cstdint>

#define NN 25000
#define NE 400000
#define HD 128
#define LN_EPS 1e-5f

// ================= device scratch =================
__device__ int   g_src[NE];
__device__ int   g_dst[NE];
__device__ int   g_is64;
__device__ float g_eA[(size_t)NE * HD];
__device__ float g_eB[(size_t)NE * HD];
__device__ float g_agg[(size_t)NN * HD];
__device__ float g_x[(size_t)NN * HD];

// fp16 hi/lo weight pools, [n=128][Kpad] row-major per matrix
#define POOL_ELEMS 335872
__device__ __align__(16) __half g_wh[POOL_ELEMS];
__device__ __align__(16) __half g_wl[POOL_ELEMS];

// ================= smem layout (dynamic, bytes) =================
// Tiles: 128 rows x 64 k halves, row stride 144 B (64*2 + 16 pad).
// W chunk (hi+lo) + H region of two 64-col slots (hi+lo each), updated in place.
#define SW_HI    0u
#define SW_LO    18432u
#define H_BASE   36864u
// slot s (0/1): HI = H_BASE + s*36864, LO = HI + 18432
#define SMEM_DYN 110592
#define LDT      144u
// f32 LN staging overlays H region: floats at byte 36864, stride 130 (66560 B <= 73728)

// ================= helpers =================
__device__ __forceinline__ uint32_t smem_u32(const void* p) {
    uint32_t a;
    asm("{ .reg .u64 t; cvta.to.shared.u64 t, %1; cvt.u32.u64 %0, t; }"
        : "=r"(a) : "l"(p));
    return a;
}
__device__ __forceinline__ void ldsm4(uint32_t addr, uint32_t* r) {
    asm volatile("ldmatrix.sync.aligned.m8n8.x4.shared.b16 {%0,%1,%2,%3}, [%4];"
                 : "=r"(r[0]), "=r"(r[1]), "=r"(r[2]), "=r"(r[3]) : "r"(addr));
}
__device__ __forceinline__ void mma16816(float* d, const uint32_t* a,
                                         uint32_t b0, uint32_t b1) {
    asm volatile(
        "mma.sync.aligned.m16n8k16.row.col.f32.f16.f16.f32 "
        "{%0,%1,%2,%3}, {%4,%5,%6,%7}, {%8,%9}, {%0,%1,%2,%3};"
        : "+f"(d[0]), "+f"(d[1]), "+f"(d[2]), "+f"(d[3])
        : "r"(a[0]), "r"(a[1]), "r"(a[2]), "r"(a[3]), "r"(b0), "r"(b1));
}
__device__ __forceinline__ void cp16(uint32_t dst, const void* src) {
    asm volatile("cp.async.cg.shared.global [%0], [%1], 16;"
                 :: "r"(dst), "l"(src));
}
__device__ __forceinline__ void cp_wait() {
    asm volatile("cp.async.commit_group;");
    asm volatile("cp.async.wait_group 0;" ::: "memory");
}
__device__ __forceinline__ void pack_pair(float a, float b, uint32_t& hi, uint32_t& lo) {
    __half ha = __float2half_rn(a), hb = __float2half_rn(b);
    float ra = a - __half2float(ha);
    float rb = b - __half2float(hb);
    __half2 H = __halves2half2(ha, hb);
    __half2 L = __floats2half2_rn(ra, rb);
    hi = *reinterpret_cast<uint32_t*>(&H);
    lo = *reinterpret_cast<uint32_t*>(&L);
}
__device__ __forceinline__ float silu(float v) { return v / (1.f + __expf(-v)); }

// ================= index prep =================
__global__ void detect_kernel(const int* __restrict__ raw) {
    __shared__ int cnt;
    if (threadIdx.x == 0) cnt = 0;
    __syncthreads();
    int c = 0;
    for (int t = threadIdx.x; t < 1024; t += blockDim.x)
        if (raw[2 * t + 1] != 0) c++;
    atomicAdd(&cnt, c);
    __syncthreads();
    if (threadIdx.x == 0) g_is64 = (cnt < 16) ? 1 : 0;
}
__global__ void convert_kernel(const int* __restrict__ raw) {
    int i = blockIdx.x * blockDim.x + threadIdx.x;
    if (i >= NE) return;
    int s, d;
    if (g_is64) {
        const long long* p = (const long long*)raw;
        s = (int)p[i];
        d = (int)p[NE + i];
    } else {
        s = raw[i];
        d = raw[NE + i];
    }
    if ((unsigned)s >= NN) s = 0;
    if ((unsigned)d >= NN) d = 0;
    g_src[i] = s;
    g_dst[i] = d;
}

// ================= weight split prep =================
#define NJOBS 15
struct WJob { const float* src; int Ksrc; int Kpad; int dst; };
struct WJobs { WJob j[NJOBS]; };
__global__ void conv_w_kernel(WJobs jobs) {
    WJob jb = jobs.j[blockIdx.y];
    int idx = blockIdx.x * 256 + threadIdx.x;
    if (idx >= 128 * jb.Kpad) return;
    int n = idx / jb.Kpad, k = idx % jb.Kpad;
    float v = (k < jb.Ksrc) ? jb.src[(size_t)k * 128 + n] : 0.f;
    __half h = __float2half_rn(v);
    float r = v - __half2float(h);
    g_wh[(size_t)jb.dst + (size_t)n * jb.Kpad + k] = h;
    g_wl[(size_t)jb.dst + (size_t)n * jb.Kpad + k] = __float2half_rn(r);
}

// ================= tile fill (fused gather) =================
template <int MODE>
__device__ __forceinline__ void fill_a(char* sm, const float* __restrict__ in0,
                                       const float* __restrict__ in1,
                                       int chunk, int row0, int rows, uint32_t slotBase) {
    const int t = threadIdx.x;            // 256 threads
    const int r = t >> 1;                 // 0..127
    const int kh = (t & 1) << 5;          // local k base: 0 or 32
    const int gk = chunk * 64 + kh;       // global k for this 32-col span
    const int row = row0 + r;
    const float* src = nullptr;
    if (MODE == 0) {
        if (kh == 0 && row < rows) src = in0 + (size_t)row * 16;
    } else if (MODE == 1) {
        if (row < rows) {
            int sect = gk >> 7;            // 0: x[dst], 1: x[src], 2: e
            int coff = gk & 127;
            if (sect == 0)      src = in0 + (size_t)g_dst[row] * HD + coff;
            else if (sect == 1) src = in0 + (size_t)g_src[row] * HD + coff;
            else                src = in1 + (size_t)row * HD + coff;
        }
    } else {
        if (row < rows) {
            int sect = gk >> 7;            // 0: x, 1: agg
            int coff = gk & 127;
            src = (sect ? in1 : in0) + (size_t)row * HD + coff;
        }
    }
    const uint32_t rbase = (uint32_t)r * LDT;
#pragma unroll
    for (int g = 0; g < 4; g++) {
        float4 v0 = make_float4(0.f, 0.f, 0.f, 0.f), v1 = v0;
        bool have = (src != nullptr) && !(MODE == 0 && g >= 2);
        if (have) {
            v0 = *(const float4*)(src + g * 8);
            v1 = *(const float4*)(src + g * 8 + 4);
        }
        uint32_t h[4], l[4];
        pack_pair(v0.x, v0.y, h[0], l[0]);
        pack_pair(v0.z, v0.w, h[1], l[1]);
        pack_pair(v1.x, v1.y, h[2], l[2]);
        pack_pair(v1.z, v1.w, h[3], l[3]);
        uint32_t off = rbase + (uint32_t)(kh + g * 8) * 2u;
        *(uint4*)(sm + slotBase + off)          = make_uint4(h[0], h[1], h[2], h[3]);
        *(uint4*)(sm + slotBase + 18432u + off) = make_uint4(l[0], l[1], l[2], l[3]);
    }
}

// W tile [128 n][64 k] via cp.async
__device__ __forceinline__ void load_w_async(uint32_t sb, int wofs, int kc, int Kpad) {
    const int t = threadIdx.x;
    const int n = t >> 1;
    const int kh = (t & 1) << 5;
    const __half* ph = g_wh + wofs + (size_t)n * Kpad + kc + kh;
    const __half* pl = g_wl + wofs + (size_t)n * Kpad + kc + kh;
    const uint32_t nb = (uint32_t)n * LDT;
#pragma unroll
    for (int g = 0; g < 4; g++) {
        uint32_t off = nb + (uint32_t)(kh + g * 8) * 2u;
        cp16(sb + SW_HI + off, ph + g * 8);
        cp16(sb + SW_LO + off, pl + g * 8);
    }
}

// ================= warp MMA over one 64-k chunk =================
__device__ __forceinline__ void mma_chunk(uint32_t sb, uint32_t aHi,
                                          float (&acc)[2][8][4], int m0, int n0, int lane) {
    const uint32_t aLo = aHi + 18432u;
    const int rowA = m0 + (lane & 15);
    const int kselA = (lane >> 4) << 3;
    const uint32_t aB0 = (uint32_t)rowA * LDT;
    const uint32_t aB1 = aB0 + 16u * LDT;
    const int rowB = n0 + (lane & 7) + (((lane >> 4) & 1) << 3);
    const int kselB = ((lane >> 3) & 1) << 3;
#pragma unroll
    for (int k16 = 0; k16 < 64; k16 += 16) {
        uint32_t ah[2][4], al[2][4], bh[4][4], bl[4][4];
        uint32_t ak = (uint32_t)(k16 + kselA) * 2u;
        ldsm4(sb + aHi + aB0 + ak, ah[0]);
        ldsm4(sb + aHi + aB1 + ak, ah[1]);
        ldsm4(sb + aLo + aB0 + ak, al[0]);
        ldsm4(sb + aLo + aB1 + ak, al[1]);
        uint32_t bk = (uint32_t)(k16 + kselB) * 2u;
#pragma unroll
        for (int nb = 0; nb < 4; nb++) {
            uint32_t bb = (uint32_t)(rowB + nb * 16) * LDT;
            ldsm4(sb + SW_HI + bb + bk, bh[nb]);
            ldsm4(sb + SW_LO + bb + bk, bl[nb]);
        }
#pragma unroll
        for (int mi = 0; mi < 2; mi++)
#pragma unroll
            for (int nb = 0; nb < 4; nb++) {
                mma16816(acc[mi][nb * 2],     ah[mi], bh[nb][0], bh[nb][1]);
                mma16816(acc[mi][nb * 2 + 1], ah[mi], bh[nb][2], bh[nb][3]);
                mma16816(acc[mi][nb * 2],     al[mi], bh[nb][0], bh[nb][1]);
                mma16816(acc[mi][nb * 2 + 1], al[mi], bh[nb][2], bh[nb][3]);
                mma16816(acc[mi][nb * 2],     ah[mi], bl[nb][0], bl[nb][1]);
                mma16816(acc[mi][nb * 2 + 1], ah[mi], bl[nb][2], bl[nb][3]);
            }
    }
}

// ================= epilogues =================
// SiLU epilogue writes IN PLACE into the H slots (cols 0-63 -> slot0, 64-127 -> slot1)
__device__ __forceinline__ void epi_silu(char* sm, float (&acc)[2][8][4],
                                         const float* __restrict__ bias,
                                         int m0, int n0, int lane) {
    const int cq = (lane & 3) << 1;
    const int r0l = lane >> 2;
#pragma unroll
    for (int mi = 0; mi < 2; mi++)
#pragma unroll
        for (int j = 0; j < 8; j++) {
            int c = n0 + j * 8 + cq;
            float b0 = bias[c], b1 = bias[c + 1];
            uint32_t hiT = H_BASE + (uint32_t)(c >> 6) * 36864u;
            int hc = c & 63;
#pragma unroll
            for (int h = 0; h < 2; h++) {
                float v0 = silu(acc[mi][j][2 * h] + b0);
                float v1 = silu(acc[mi][j][2 * h + 1] + b1);
                uint32_t hi, lo;
                pack_pair(v0, v1, hi, lo);
                int r = m0 + mi * 16 + r0l + 8 * h;
                uint32_t off = (uint32_t)r * LDT + (uint32_t)(hc * 2);
                *(uint32_t*)(sm + hiT + off)          = hi;
                *(uint32_t*)(sm + hiT + 18432u + off) = lo;
            }
        }
}

__device__ __forceinline__ void epi_ln(char* sm, float (&acc)[2][8][4],
                                       const float* __restrict__ bias,
                                       const float* __restrict__ gam,
                                       const float* __restrict__ bet,
                                       float (*sRed)[128][2],
                                       int m0, int n0, int wn, int lane) {
    const int cq = (lane & 3) << 1;
    const int r0l = lane >> 2;
    float s[2][2] = {{0.f, 0.f}, {0.f, 0.f}};
    float q[2][2] = {{0.f, 0.f}, {0.f, 0.f}};
#pragma unroll
    for (int mi = 0; mi < 2; mi++)
#pragma unroll
        for (int j = 0; j < 8; j++) {
            int c = n0 + j * 8 + cq;
            float b0 = bias[c], b1 = bias[c + 1];
#pragma unroll
            for (int h = 0; h < 2; h++) {
                float v0 = acc[mi][j][2 * h] + b0;
                float v1 = acc[mi][j][2 * h + 1] + b1;
                s[mi][h] += v0 + v1;
                q[mi][h] += v0 * v0 + v1 * v1;
            }
        }
#pragma unroll
    for (int o = 1; o <= 2; o <<= 1)
#pragma unroll
        for (int mi = 0; mi < 2; mi++)
#pragma unroll
            for (int h = 0; h < 2; h++) {
                s[mi][h] += __shfl_xor_sync(0xffffffffu, s[mi][h], o);
                q[mi][h] += __shfl_xor_sync(0xffffffffu, q[mi][h], o);
            }
    if ((lane & 3) == 0) {
#pragma unroll
        for (int mi = 0; mi < 2; mi++)
#pragma unroll
            for (int h = 0; h < 2; h++) {
                int r = m0 + mi * 16 + r0l + 8 * h;
                sRed[wn][r][0] = s[mi][h];
                sRed[wn][r][1] = q[mi][h];
            }
    }
    __syncthreads();
    float mu[2][2], rs[2][2];
#pragma unroll
    for (int mi = 0; mi < 2; mi++)
#pragma unroll
        for (int h = 0; h < 2; h++) {
            int r = m0 + mi * 16 + r0l + 8 * h;
            float S = sRed[0][r][0] + sRed[1][r][0];
            float Q = sRed[0][r][1] + sRed[1][r][1];
            float m = S * (1.f / HD);
            float var = Q * (1.f / HD) - m * m;
            mu[mi][h] = m;
            rs[mi][h] = rsqrtf(var + LN_EPS);
        }
    float* so = (float*)(sm + H_BASE);  // stride 130 floats, 66560 B <= 73728
#pragma unroll
    for (int mi = 0; mi < 2; mi++)
#pragma unroll
        for (int j = 0; j < 8; j++) {
            int c = n0 + j * 8 + cq;
            float b0 = bias[c], b1 = bias[c + 1];
            float g0 = gam[c], g1 = gam[c + 1];
            float e0 = bet[c], e1 = bet[c + 1];
#pragma unroll
            for (int h = 0; h < 2; h++) {
                int r = m0 + mi * 16 + r0l + 8 * h;
                float v0 = acc[mi][j][2 * h] + b0;
                float v1 = acc[mi][j][2 * h + 1] + b1;
                so[r * 130 + c]     = (v0 - mu[mi][h]) * rs[mi][h] * g0 + e0;
                so[r * 130 + c + 1] = (v1 - mu[mi][h]) * rs[mi][h] * g1 + e1;
            }
        }
}

// ================= fused MLP kernel =================
template <int MODE, int NCH>
__global__ __launch_bounds__(256, 2) void mma_mlp(
    const float* __restrict__ in0, const float* __restrict__ in1,
    int o1, int o2, int o3, int Kpad1,
    const float* __restrict__ b1, const float* __restrict__ b2,
    const float* __restrict__ b3, const float* __restrict__ gam,
    const float* __restrict__ bet,
    const float* __restrict__ resid, float* __restrict__ out, int rows) {
    extern __shared__ char sm[];
    __shared__ float sRed[2][128][2];
    const int t = threadIdx.x;
    const uint32_t sb = smem_u32(sm);
    const int lane = t & 31, w = t >> 5;
    const int m0 = (w & 3) * 32, n0 = (w >> 2) * 64, wn = w >> 2;
    const int row0 = blockIdx.x * 128;
    float acc[2][8][4];

    // ---- layer 1: K = NCH*64 -> 128, SiLU -> H slots (in place) ----
#pragma unroll
    for (int mi = 0; mi < 2; mi++)
        for (int j = 0; j < 8; j++)
            for (int e = 0; e < 4; e++) acc[mi][j][e] = 0.f;
    for (int c = 0; c < NCH; c++) {
        __syncthreads();
        uint32_t slot = H_BASE + (uint32_t)(c & 1) * 36864u;
        load_w_async(sb, o1, c * 64, Kpad1);
        fill_a<MODE>(sm, in0, in1, c, row0, rows, slot);
        cp_wait();
        __syncthreads();
        mma_chunk(sb, slot, acc, m0, n0, lane);
    }
    __syncthreads();
    epi_silu(sm, acc, b1, m0, n0, lane);

    // ---- layer 2: 128 -> 128, SiLU (in place) ----
#pragma unroll
    for (int mi = 0; mi < 2; mi++)
        for (int j = 0; j < 8; j++)
            for (int e = 0; e < 4; e++) acc[mi][j][e] = 0.f;
    for (int c = 0; c < 2; c++) {
        __syncthreads();
        load_w_async(sb, o2, c * 64, 128);
        cp_wait();
        __syncthreads();
        mma_chunk(sb, H_BASE + (uint32_t)c * 36864u, acc, m0, n0, lane);
    }
    __syncthreads();
    epi_silu(sm, acc, b2, m0, n0, lane);

    // ---- layer 3: 128 -> 128, LayerNorm -> staging ----
#pragma unroll
    for (int mi = 0; mi < 2; mi++)
        for (int j = 0; j < 8; j++)
            for (int e = 0; e < 4; e++) acc[mi][j][e] = 0.f;
    for (int c = 0; c < 2; c++) {
        __syncthreads();
        load_w_async(sb, o3, c * 64, 128);
        cp_wait();
        __syncthreads();
        mma_chunk(sb, H_BASE + (uint32_t)c * 36864u, acc, m0, n0, lane);
    }
    __syncthreads();
    epi_ln(sm, acc, b3, gam, bet, sRed, m0, n0, wn, lane);
    __syncthreads();

    // ---- residual + coalesced store ----
    const float* so = (const float*)(sm + H_BASE);
    const int col = t & 127;
    for (int r = (t >> 7); r < 128; r += 2) {
        int row = row0 + r;
        if (row < rows) {
            float y = so[r * 130 + col];
            if (MODE != 0) y += resid[(size_t)row * HD + col];
            out[(size_t)row * HD + col] = y;
        }
    }
}

// ================= aggregation =================
__global__ void zero_agg_kernel() {
    size_t i = (size_t)blockIdx.x * blockDim.x + threadIdx.x;
    if (i < (size_t)NN * HD) g_agg[i] = 0.f;
}
__global__ void scatter_kernel(const float* __restrict__ e) {
    size_t i = (size_t)blockIdx.x * blockDim.x + threadIdx.x;
    if (i >= (size_t)NE * HD) return;
    int edge = (int)(i >> 7);
    int c = (int)(i & 127);
    atomicAdd(&g_agg[(size_t)g_dst[edge] * HD + c], e[i]);
}

// ================= launch =================
extern "C" void kernel_launch(void* const* d_in, const int* in_sizes, int n_in,
                              void* d_out, int out_size) {
    const float* x_in    = (const float*)d_in[0];
    const int*   eidx    = (const int*)d_in[1];
    const float* eattr   = (const float*)d_in[2];
    const float* emb_W1  = (const float*)d_in[3];
    const float* emb_b1  = (const float*)d_in[4];
    const float* emb_W2  = (const float*)d_in[5];
    const float* emb_b2  = (const float*)d_in[6];
    const float* emb_W3  = (const float*)d_in[7];
    const float* emb_b3  = (const float*)d_in[8];
    const float* emb_g   = (const float*)d_in[9];
    const float* emb_be  = (const float*)d_in[10];
    const float* edge_W1 = (const float*)d_in[11];
    const float* edge_b1 = (const float*)d_in[12];
    const float* edge_W2 = (const float*)d_in[13];
    const float* edge_b2 = (const float*)d_in[14];
    const float* edge_W3 = (const float*)d_in[15];
    const float* edge_b3 = (const float*)d_in[16];
    const float* edge_g  = (const float*)d_in[17];
    const float* edge_be = (const float*)d_in[18];
    const float* node_W1 = (const float*)d_in[19];
    const float* node_b1 = (const float*)d_in[20];
    const float* node_W2 = (const float*)d_in[21];
    const float* node_b2 = (const float*)d_in[22];
    const float* node_W3 = (const float*)d_in[23];
    const float* node_b3 = (const float*)d_in[24];
    const float* node_g  = (const float*)d_in[25];
    const float* node_be = (const float*)d_in[26];

    float* out_x = (float*)d_out;
    float* out_e = (float*)d_out + (size_t)NN * HD;

    float *eA, *eB, *agg, *xbuf;
    cudaGetSymbolAddress((void**)&eA, g_eA);
    cudaGetSymbolAddress((void**)&eB, g_eB);
    cudaGetSymbolAddress((void**)&agg, g_agg);
    cudaGetSymbolAddress((void**)&xbuf, g_x);

    cudaFuncSetAttribute(mma_mlp<0, 1>, cudaFuncAttributeMaxDynamicSharedMemorySize, SMEM_DYN);
    cudaFuncSetAttribute(mma_mlp<1, 6>, cudaFuncAttributeMaxDynamicSharedMemorySize, SMEM_DYN);
    cudaFuncSetAttribute(mma_mlp<2, 4>, cudaFuncAttributeMaxDynamicSharedMemorySize, SMEM_DYN);

    // index prep (clamped)
    detect_kernel<<<1, 256>>>(eidx);
    convert_kernel<<<(NE + 255) / 256, 256>>>(eidx);

    // pool offsets (elements)
    const int oEmb1 = 0, oEmb2 = 8192, oEmb3 = 24576;
    int oE1[2], oE2[2], oE3[2], oN1[2], oN2[2], oN3[2];
    int base = 40960;
    for (int l = 0; l < 2; l++) {
        oE1[l] = base;
        oE2[l] = base + 49152;
        oE3[l] = base + 65536;
        oN1[l] = base + 81920;
        oN2[l] = base + 114688;
        oN3[l] = base + 131072;
        base += 147456;
    }

    WJobs jobs;
    int ji = 0;
    jobs.j[ji++] = {emb_W1, 16, 64, oEmb1};
    jobs.j[ji++] = {emb_W2, 128, 128, oEmb2};
    jobs.j[ji++] = {emb_W3, 128, 128, oEmb3};
    for (int l = 0; l < 2; l++) {
        jobs.j[ji++] = {edge_W1 + (size_t)l * 3 * HD * HD, 384, 384, oE1[l]};
        jobs.j[ji++] = {edge_W2 + (size_t)l * HD * HD, 128, 128, oE2[l]};
        jobs.j[ji++] = {edge_W3 + (size_t)l * HD * HD, 128, 128, oE3[l]};
        jobs.j[ji++] = {node_W1 + (size_t)l * 2 * HD * HD, 256, 256, oN1[l]};
        jobs.j[ji++] = {node_W2 + (size_t)l * HD * HD, 128, 128, oN2[l]};
        jobs.j[ji++] = {node_W3 + (size_t)l * HD * HD, 128, 128, oN3[l]};
    }
    dim3 cg((128 * 384 + 255) / 256, NJOBS);
    conv_w_kernel<<<cg, 256>>>(jobs);

    const int edge_blocks = NE / 128;           // 3125
    const int node_blocks = (NN + 127) / 128;   // 196
    const int ethr_blocks = (int)(((size_t)NE * HD + 255) / 256);
    const int nthr_blocks = (int)(((size_t)NN * HD + 255) / 256);

    // edge embedding: e = MLP(edge_attr)
    mma_mlp<0, 1><<<edge_blocks, 256, SMEM_DYN>>>(
        eattr, nullptr, oEmb1, oEmb2, oEmb3, 64,
        emb_b1, emb_b2, emb_b3, emb_g, emb_be, nullptr, eA, NE);

    const float* x_cur = x_in;
    float* e_cur = eA;
    for (int l = 0; l < 2; l++) {
        float* e_out = (l == 0) ? eB : out_e;
        float* x_out = (l == 0) ? xbuf : out_x;

        // e_new = MLP([x[dst] | x[src] | e]) + e
        mma_mlp<1, 6><<<edge_blocks, 256, SMEM_DYN>>>(
            x_cur, e_cur, oE1[l], oE2[l], oE3[l], 384,
            edge_b1 + l * HD, edge_b2 + l * HD, edge_b3 + l * HD,
            edge_g + l * HD, edge_be + l * HD, e_cur, e_out, NE);

        // agg = segment_sum(e_new, dst)
        zero_agg_kernel<<<nthr_blocks, 256>>>();
        scatter_kernel<<<ethr_blocks, 256>>>(e_out);

        // x = MLP([x | agg]) + x
        mma_mlp<2, 4><<<node_blocks, 256, SMEM_DYN>>>(
            x_cur, agg, oN1[l], oN2[l], oN3[l], 256,
            node_b1 + l * HD, node_b2 + l * HD, node_b3 + l * HD,
            node_g + l * HD, node_be + l * HD, x_cur, x_out, NN);

        e_cur = e_out;
        x_cur = x_out;
    }
}

// round 9
// speedup vs baseline: 2.8060x; 1.1353x over previous
#include <cuda_runtime.h>
#include <cuda_fp16.h>
#include <cstdint>

#define NN 25000
#define NE 400000
#define HD 128
#define LN_EPS 1e-5f

// ================= device scratch =================
__device__ int   g_src[NE];
__device__ int   g_dst[NE];
__device__ int   g_is64;
__device__ float g_eA[(size_t)NE * HD];
__device__ float g_eB[(size_t)NE * HD];
__device__ float g_agg[(size_t)NN * HD];
__device__ float g_x[(size_t)NN * HD];

// fp16 hi/lo weight pools, [n=128][Kpad] row-major per matrix
#define POOL_ELEMS 335872
__device__ __align__(16) __half g_wh[POOL_ELEMS];
__device__ __align__(16) __half g_wl[POOL_ELEMS];

// ================= smem layout (dynamic, bytes) =================
// Tiles: 128 rows x 64 k halves, row stride 144 B. Each tile pair = hi at base,
// lo at base+18432. W double buffer + two A/H slots.
#define LDT      144u
#define WB(i)    ((uint32_t)(i) * 36864u)            // 0, 36864
#define SL(i)    (73728u + (uint32_t)(i) * 36864u)   // 73728, 110592
#define SMEM_DYN 147456
// f32 LN staging overlays slot region: floats at byte 73728, stride 130 (66560 B)

// ================= helpers =================
__device__ __forceinline__ uint32_t smem_u32(const void* p) {
    uint32_t a;
    asm("{ .reg .u64 t; cvta.to.shared.u64 t, %1; cvt.u32.u64 %0, t; }"
        : "=r"(a) : "l"(p));
    return a;
}
__device__ __forceinline__ void ldsm4(uint32_t addr, uint32_t* r) {
    asm volatile("ldmatrix.sync.aligned.m8n8.x4.shared.b16 {%0,%1,%2,%3}, [%4];"
                 : "=r"(r[0]), "=r"(r[1]), "=r"(r[2]), "=r"(r[3]) : "r"(addr));
}
__device__ __forceinline__ void mma16816(float* d, const uint32_t* a,
                                         uint32_t b0, uint32_t b1) {
    asm volatile(
        "mma.sync.aligned.m16n8k16.row.col.f32.f16.f16.f32 "
        "{%0,%1,%2,%3}, {%4,%5,%6,%7}, {%8,%9}, {%0,%1,%2,%3};"
        : "+f"(d[0]), "+f"(d[1]), "+f"(d[2]), "+f"(d[3])
        : "r"(a[0]), "r"(a[1]), "r"(a[2]), "r"(a[3]), "r"(b0), "r"(b1));
}
__device__ __forceinline__ void cp16(uint32_t dst, const void* src) {
    asm volatile("cp.async.cg.shared.global [%0], [%1], 16;"
                 :: "r"(dst), "l"(src));
}
#define CP_COMMIT() asm volatile("cp.async.commit_group;")
#define CP_WAIT0()  asm volatile("cp.async.wait_group 0;" ::: "memory")
__device__ __forceinline__ void pack_pair(float a, float b, uint32_t& hi, uint32_t& lo) {
    __half ha = __float2half_rn(a), hb = __float2half_rn(b);
    float ra = a - __half2float(ha);
    float rb = b - __half2float(hb);
    __half2 H = __halves2half2(ha, hb);
    __half2 L = __floats2half2_rn(ra, rb);
    hi = *reinterpret_cast<uint32_t*>(&H);
    lo = *reinterpret_cast<uint32_t*>(&L);
}
__device__ __forceinline__ float silu(float v) { return v / (1.f + __expf(-v)); }

// ================= index prep =================
__global__ void detect_kernel(const int* __restrict__ raw) {
    __shared__ int cnt;
    if (threadIdx.x == 0) cnt = 0;
    __syncthreads();
    int c = 0;
    for (int t = threadIdx.x; t < 1024; t += blockDim.x)
        if (raw[2 * t + 1] != 0) c++;
    atomicAdd(&cnt, c);
    __syncthreads();
    if (threadIdx.x == 0) g_is64 = (cnt < 16) ? 1 : 0;
}
__global__ void convert_kernel(const int* __restrict__ raw) {
    int i = blockIdx.x * blockDim.x + threadIdx.x;
    if (i >= NE) return;
    int s, d;
    if (g_is64) {
        const long long* p = (const long long*)raw;
        s = (int)p[i];
        d = (int)p[NE + i];
    } else {
        s = raw[i];
        d = raw[NE + i];
    }
    if ((unsigned)s >= NN) s = 0;
    if ((unsigned)d >= NN) d = 0;
    g_src[i] = s;
    g_dst[i] = d;
}

// ================= weight split prep =================
#define NJOBS 15
struct WJob { const float* src; int Ksrc; int Kpad; int dst; };
struct WJobs { WJob j[NJOBS]; };
__global__ void conv_w_kernel(WJobs jobs) {
    WJob jb = jobs.j[blockIdx.y];
    int idx = blockIdx.x * 256 + threadIdx.x;
    if (idx >= 128 * jb.Kpad) return;
    int n = idx / jb.Kpad, k = idx % jb.Kpad;
    float v = (k < jb.Ksrc) ? jb.src[(size_t)k * 128 + n] : 0.f;
    __half h = __float2half_rn(v);
    float r = v - __half2float(h);
    g_wh[(size_t)jb.dst + (size_t)n * jb.Kpad + k] = h;
    g_wl[(size_t)jb.dst + (size_t)n * jb.Kpad + k] = __float2half_rn(r);
}

// ================= A gather: load phase (regs) =================
// 512 threads: r = t>>2 (0..127), 16 k-halves per thread.
template <int MODE>
__device__ __forceinline__ void a_load(const float* __restrict__ in0,
                                       const float* __restrict__ in1,
                                       int chunk, int row0, int rows, int t,
                                       float4* v) {
    const int r = t >> 2;
    const int kh = (t & 3) << 4;          // 0,16,32,48
    const int gk = chunk * 64 + kh;
    const int row = row0 + r;
    const float* src = nullptr;
    if (MODE == 0) {
        if (kh == 0 && row < rows) src = in0 + (size_t)row * 16;
    } else if (MODE == 1) {
        if (row < rows) {
            int sect = gk >> 7;
            int coff = gk & 127;
            if (sect == 0)      src = in0 + (size_t)g_dst[row] * HD + coff;
            else if (sect == 1) src = in0 + (size_t)g_src[row] * HD + coff;
            else                src = in1 + (size_t)row * HD + coff;
        }
    } else {
        if (row < rows) {
            int sect = gk >> 7;
            int coff = gk & 127;
            src = (sect ? in1 : in0) + (size_t)row * HD + coff;
        }
    }
    v[0] = v[1] = v[2] = v[3] = make_float4(0.f, 0.f, 0.f, 0.f);
    if (src) {
        v[0] = *(const float4*)(src);
        v[1] = *(const float4*)(src + 4);
        v[2] = *(const float4*)(src + 8);
        v[3] = *(const float4*)(src + 12);
    }
}

// A gather: pack + store phase
__device__ __forceinline__ void a_store(char* sm, uint32_t slot, int t, const float4* v) {
    const int r = t >> 2;
    const int kh = (t & 3) << 4;
    const uint32_t rbase = (uint32_t)r * LDT;
#pragma unroll
    for (int g = 0; g < 2; g++) {
        uint32_t h[4], l[4];
        pack_pair(v[2 * g].x,     v[2 * g].y,     h[0], l[0]);
        pack_pair(v[2 * g].z,     v[2 * g].w,     h[1], l[1]);
        pack_pair(v[2 * g + 1].x, v[2 * g + 1].y, h[2], l[2]);
        pack_pair(v[2 * g + 1].z, v[2 * g + 1].w, h[3], l[3]);
        uint32_t off = rbase + (uint32_t)(kh + g * 8) * 2u;
        *(uint4*)(sm + slot + off)          = make_uint4(h[0], h[1], h[2], h[3]);
        *(uint4*)(sm + slot + 18432u + off) = make_uint4(l[0], l[1], l[2], l[3]);
    }
}

// W tile via cp.async (512 threads)
__device__ __forceinline__ void load_w_async(uint32_t sb, uint32_t wb,
                                             int wofs, int kc, int Kpad, int t) {
    const int n = t >> 2;
    const int kh = (t & 3) << 4;
    const __half* ph = g_wh + wofs + (size_t)n * Kpad + kc + kh;
    const __half* pl = g_wl + wofs + (size_t)n * Kpad + kc + kh;
    const uint32_t nb = (uint32_t)n * LDT;
#pragma unroll
    for (int g = 0; g < 2; g++) {
        uint32_t off = nb + (uint32_t)(kh + g * 8) * 2u;
        cp16(sb + wb + off, ph + g * 8);
        cp16(sb + wb + 18432u + off, pl + g * 8);
    }
}

// ================= warp MMA over one 64-k chunk (warp tile 32x32) =================
__device__ __forceinline__ void mma_chunk(uint32_t sb, uint32_t aB, uint32_t wB,
                                          float (&acc)[2][4][4], int m0, int n0, int lane) {
    const uint32_t aLo = aB + 18432u;
    const uint32_t wLo = wB + 18432u;
    const int rowA = m0 + (lane & 15);
    const int kselA = (lane >> 4) << 3;
    const uint32_t aB0 = (uint32_t)rowA * LDT;
    const uint32_t aB1 = aB0 + 16u * LDT;
    const int rowB = n0 + (lane & 7) + (((lane >> 4) & 1) << 3);
    const int kselB = ((lane >> 3) & 1) << 3;
#pragma unroll
    for (int k16 = 0; k16 < 64; k16 += 16) {
        uint32_t ah[2][4], al[2][4], bh[2][4], bl[2][4];
        uint32_t ak = (uint32_t)(k16 + kselA) * 2u;
        ldsm4(sb + aB + aB0 + ak, ah[0]);
        ldsm4(sb + aB + aB1 + ak, ah[1]);
        ldsm4(sb + aLo + aB0 + ak, al[0]);
        ldsm4(sb + aLo + aB1 + ak, al[1]);
        uint32_t bk = (uint32_t)(k16 + kselB) * 2u;
#pragma unroll
        for (int nb = 0; nb < 2; nb++) {
            uint32_t bb = (uint32_t)(rowB + nb * 16) * LDT;
            ldsm4(sb + wB + bb + bk, bh[nb]);
            ldsm4(sb + wLo + bb + bk, bl[nb]);
        }
#pragma unroll
        for (int mi = 0; mi < 2; mi++)
#pragma unroll
            for (int nb = 0; nb < 2; nb++) {
                mma16816(acc[mi][nb * 2],     ah[mi], bh[nb][0], bh[nb][1]);
                mma16816(acc[mi][nb * 2 + 1], ah[mi], bh[nb][2], bh[nb][3]);
                mma16816(acc[mi][nb * 2],     al[mi], bh[nb][0], bh[nb][1]);
                mma16816(acc[mi][nb * 2 + 1], al[mi], bh[nb][2], bh[nb][3]);
                mma16816(acc[mi][nb * 2],     ah[mi], bl[nb][0], bl[nb][1]);
                mma16816(acc[mi][nb * 2 + 1], ah[mi], bl[nb][2], bl[nb][3]);
            }
    }
}

__device__ __forceinline__ void zero_acc(float (&acc)[2][4][4]) {
#pragma unroll
    for (int mi = 0; mi < 2; mi++)
#pragma unroll
        for (int j = 0; j < 4; j++)
#pragma unroll
            for (int e = 0; e < 4; e++) acc[mi][j][e] = 0.f;
}

// ================= epilogues =================
__device__ __forceinline__ void epi_silu(char* sm, float (&acc)[2][4][4],
                                         const float* __restrict__ bias,
                                         int m0, int n0, int lane) {
    const int cq = (lane & 3) << 1;
    const int r0l = lane >> 2;
#pragma unroll
    for (int mi = 0; mi < 2; mi++)
#pragma unroll
        for (int j = 0; j < 4; j++) {
            int c = n0 + j * 8 + cq;
            float b0 = bias[c], b1 = bias[c + 1];
            uint32_t hiT = SL(c >> 6);
            int hc = c & 63;
#pragma unroll
            for (int h = 0; h < 2; h++) {
                float v0 = silu(acc[mi][j][2 * h] + b0);
                float v1 = silu(acc[mi][j][2 * h + 1] + b1);
                uint32_t hi, lo;
                pack_pair(v0, v1, hi, lo);
                int r = m0 + mi * 16 + r0l + 8 * h;
                uint32_t off = (uint32_t)r * LDT + (uint32_t)(hc * 2);
                *(uint32_t*)(sm + hiT + off)          = hi;
                *(uint32_t*)(sm + hiT + 18432u + off) = lo;
            }
        }
}

__device__ __forceinline__ void epi_ln(char* sm, float (&acc)[2][4][4],
                                       const float* __restrict__ bias,
                                       const float* __restrict__ gam,
                                       const float* __restrict__ bet,
                                       float (*sRed)[128][2],
                                       int m0, int n0, int wn, int lane) {
    const int cq = (lane & 3) << 1;
    const int r0l = lane >> 2;
    float s[2][2] = {{0.f, 0.f}, {0.f, 0.f}};
    float q[2][2] = {{0.f, 0.f}, {0.f, 0.f}};
#pragma unroll
    for (int mi = 0; mi < 2; mi++)
#pragma unroll
        for (int j = 0; j < 4; j++) {
            int c = n0 + j * 8 + cq;
            float b0 = bias[c], b1 = bias[c + 1];
#pragma unroll
            for (int h = 0; h < 2; h++) {
                float v0 = acc[mi][j][2 * h] + b0;
                float v1 = acc[mi][j][2 * h + 1] + b1;
                s[mi][h] += v0 + v1;
                q[mi][h] += v0 * v0 + v1 * v1;
            }
        }
#pragma unroll
    for (int o = 1; o <= 2; o <<= 1)
#pragma unroll
        for (int mi = 0; mi < 2; mi++)
#pragma unroll
            for (int h = 0; h < 2; h++) {
                s[mi][h] += __shfl_xor_sync(0xffffffffu, s[mi][h], o);
                q[mi][h] += __shfl_xor_sync(0xffffffffu, q[mi][h], o);
            }
    if ((lane & 3) == 0) {
#pragma unroll
        for (int mi = 0; mi < 2; mi++)
#pragma unroll
            for (int h = 0; h < 2; h++) {
                int r = m0 + mi * 16 + r0l + 8 * h;
                sRed[wn][r][0] = s[mi][h];
                sRed[wn][r][1] = q[mi][h];
            }
    }
    __syncthreads();
    float mu[2][2], rs[2][2];
#pragma unroll
    for (int mi = 0; mi < 2; mi++)
#pragma unroll
        for (int h = 0; h < 2; h++) {
            int r = m0 + mi * 16 + r0l + 8 * h;
            float S = sRed[0][r][0] + sRed[1][r][0] + sRed[2][r][0] + sRed[3][r][0];
            float Q = sRed[0][r][1] + sRed[1][r][1] + sRed[2][r][1] + sRed[3][r][1];
            float m = S * (1.f / HD);
            float var = Q * (1.f / HD) - m * m;
            mu[mi][h] = m;
            rs[mi][h] = rsqrtf(var + LN_EPS);
        }
    float* so = (float*)(sm + 73728u);  // stride 130 floats, 66560 B <= 73728
#pragma unroll
    for (int mi = 0; mi < 2; mi++)
#pragma unroll
        for (int j = 0; j < 4; j++) {
            int c = n0 + j * 8 + cq;
            float b0 = bias[c], b1 = bias[c + 1];
            float g0 = gam[c], g1 = gam[c + 1];
            float e0 = bet[c], e1 = bet[c + 1];
#pragma unroll
            for (int h = 0; h < 2; h++) {
                int r = m0 + mi * 16 + r0l + 8 * h;
                float v0 = acc[mi][j][2 * h] + b0;
                float v1 = acc[mi][j][2 * h + 1] + b1;
                so[r * 130 + c]     = (v0 - mu[mi][h]) * rs[mi][h] * g0 + e0;
                so[r * 130 + c + 1] = (v1 - mu[mi][h]) * rs[mi][h] * g1 + e1;
            }
        }
}

// ================= fused MLP kernel (512 threads, pipelined) =================
template <int MODE, int NCH>
__global__ __launch_bounds__(512, 1) void mma_mlp(
    const float* __restrict__ in0, const float* __restrict__ in1,
    int o1, int o2, int o3, int Kpad1,
    const float* __restrict__ b1, const float* __restrict__ b2,
    const float* __restrict__ b3, const float* __restrict__ gam,
    const float* __restrict__ bet,
    const float* __restrict__ resid, float* __restrict__ out, int rows) {
    extern __shared__ char sm[];
    __shared__ float sRed[4][128][2];
    const int t = threadIdx.x;
    const uint32_t sb = smem_u32(sm);
    const int lane = t & 31, w = t >> 5;
    const int m0 = (w & 3) * 32, n0 = (w >> 2) * 32, wn = w >> 2;
    const int row0 = blockIdx.x * 128;
    float acc[2][4][4];
    float4 v[4];

    // ---- layer 1: pipelined chunks, one sync each ----
    zero_acc(acc);
    for (int c = 0; c < NCH; c++) {
        __syncthreads();
        a_load<MODE>(in0, in1, c, row0, rows, t, v);
        load_w_async(sb, WB(c & 1), o1, c * 64, Kpad1, t);
        CP_COMMIT();
        if (c > 0) mma_chunk(sb, SL((c - 1) & 1), WB((c - 1) & 1), acc, m0, n0, lane);
        CP_WAIT0();
        a_store((char*)sm, SL(c & 1), t, v);
    }
    __syncthreads();
    mma_chunk(sb, SL((NCH - 1) & 1), WB((NCH - 1) & 1), acc, m0, n0, lane);
    __syncthreads();

    // ---- layer 2 ----
    load_w_async(sb, WB(0), o2, 0, 128, t);
    load_w_async(sb, WB(1), o2, 64, 128, t);
    CP_COMMIT();
    epi_silu((char*)sm, acc, b1, m0, n0, lane);
    zero_acc(acc);
    CP_WAIT0();
    __syncthreads();
    mma_chunk(sb, SL(0), WB(0), acc, m0, n0, lane);
    mma_chunk(sb, SL(1), WB(1), acc, m0, n0, lane);
    __syncthreads();

    // ---- layer 3 ----
    load_w_async(sb, WB(0), o3, 0, 128, t);
    load_w_async(sb, WB(1), o3, 64, 128, t);
    CP_COMMIT();
    epi_silu((char*)sm, acc, b2, m0, n0, lane);
    zero_acc(acc);
    CP_WAIT0();
    __syncthreads();
    mma_chunk(sb, SL(0), WB(0), acc, m0, n0, lane);
    mma_chunk(sb, SL(1), WB(1), acc, m0, n0, lane);
    __syncthreads();
    epi_ln((char*)sm, acc, b3, gam, bet, sRed, m0, n0, wn, lane);
    __syncthreads();

    // ---- residual + coalesced store ----
    const float* so = (const float*)(sm + 73728u);
    const int col = t & 127;
    for (int r = (t >> 7); r < 128; r += 4) {
        int row = row0 + r;
        if (row < rows) {
            float y = so[r * 130 + col];
            if (MODE != 0) y += resid[(size_t)row * HD + col];
            out[(size_t)row * HD + col] = y;
        }
    }
}

// ================= aggregation =================
__global__ void zero_agg_kernel() {
    size_t i = (size_t)blockIdx.x * blockDim.x + threadIdx.x;
    if (i < (size_t)NN * HD) g_agg[i] = 0.f;
}
// vectorized scatter: one red.v4 per 4 floats
__global__ void scatter_kernel(const float* __restrict__ e) {
    size_t i = (size_t)blockIdx.x * blockDim.x + threadIdx.x;
    if (i >= (size_t)NE * (HD / 4)) return;
    int edge = (int)(i >> 5);
    int c = (int)(i & 31) << 2;
    float4 val = *(const float4*)(e + (size_t)edge * HD + c);
    float* p = g_agg + (size_t)g_dst[edge] * HD + c;
    asm volatile("red.global.add.v4.f32 [%0], {%1, %2, %3, %4};"
                 :: "l"(p), "f"(val.x), "f"(val.y), "f"(val.z), "f"(val.w)
                 : "memory");
}

// ================= launch =================
extern "C" void kernel_launch(void* const* d_in, const int* in_sizes, int n_in,
                              void* d_out, int out_size) {
    const float* x_in    = (const float*)d_in[0];
    const int*   eidx    = (const int*)d_in[1];
    const float* eattr   = (const float*)d_in[2];
    const float* emb_W1  = (const float*)d_in[3];
    const float* emb_b1  = (const float*)d_in[4];
    const float* emb_W2  = (const float*)d_in[5];
    const float* emb_b2  = (const float*)d_in[6];
    const float* emb_W3  = (const float*)d_in[7];
    const float* emb_b3  = (const float*)d_in[8];
    const float* emb_g   = (const float*)d_in[9];
    const float* emb_be  = (const float*)d_in[10];
    const float* edge_W1 = (const float*)d_in[11];
    const float* edge_b1 = (const float*)d_in[12];
    const float* edge_W2 = (const float*)d_in[13];
    const float* edge_b2 = (const float*)d_in[14];
    const float* edge_W3 = (const float*)d_in[15];
    const float* edge_b3 = (const float*)d_in[16];
    const float* edge_g  = (const float*)d_in[17];
    const float* edge_be = (const float*)d_in[18];
    const float* node_W1 = (const float*)d_in[19];
    const float* node_b1 = (const float*)d_in[20];
    const float* node_W2 = (const float*)d_in[21];
    const float* node_b2 = (const float*)d_in[22];
    const float* node_W3 = (const float*)d_in[23];
    const float* node_b3 = (const float*)d_in[24];
    const float* node_g  = (const float*)d_in[25];
    const float* node_be = (const float*)d_in[26];

    float* out_x = (float*)d_out;
    float* out_e = (float*)d_out + (size_t)NN * HD;

    float *eA, *eB, *agg, *xbuf;
    cudaGetSymbolAddress((void**)&eA, g_eA);
    cudaGetSymbolAddress((void**)&eB, g_eB);
    cudaGetSymbolAddress((void**)&agg, g_agg);
    cudaGetSymbolAddress((void**)&xbuf, g_x);

    cudaFuncSetAttribute(mma_mlp<0, 1>, cudaFuncAttributeMaxDynamicSharedMemorySize, SMEM_DYN);
    cudaFuncSetAttribute(mma_mlp<1, 6>, cudaFuncAttributeMaxDynamicSharedMemorySize, SMEM_DYN);
    cudaFuncSetAttribute(mma_mlp<2, 4>, cudaFuncAttributeMaxDynamicSharedMemorySize, SMEM_DYN);

    // index prep (clamped)
    detect_kernel<<<1, 256>>>(eidx);
    convert_kernel<<<(NE + 255) / 256, 256>>>(eidx);

    // pool offsets (elements)
    const int oEmb1 = 0, oEmb2 = 8192, oEmb3 = 24576;
    int oE1[2], oE2[2], oE3[2], oN1[2], oN2[2], oN3[2];
    int base = 40960;
    for (int l = 0; l < 2; l++) {
        oE1[l] = base;
        oE2[l] = base + 49152;
        oE3[l] = base + 65536;
        oN1[l] = base + 81920;
        oN2[l] = base + 114688;
        oN3[l] = base + 131072;
        base += 147456;
    }

    WJobs jobs;
    int ji = 0;
    jobs.j[ji++] = {emb_W1, 16, 64, oEmb1};
    jobs.j[ji++] = {emb_W2, 128, 128, oEmb2};
    jobs.j[ji++] = {emb_W3, 128, 128, oEmb3};
    for (int l = 0; l < 2; l++) {
        jobs.j[ji++] = {edge_W1 + (size_t)l * 3 * HD * HD, 384, 384, oE1[l]};
        jobs.j[ji++] = {edge_W2 + (size_t)l * HD * HD, 128, 128, oE2[l]};
        jobs.j[ji++] = {edge_W3 + (size_t)l * HD * HD, 128, 128, oE3[l]};
        jobs.j[ji++] = {node_W1 + (size_t)l * 2 * HD * HD, 256, 256, oN1[l]};
        jobs.j[ji++] = {node_W2 + (size_t)l * HD * HD, 128, 128, oN2[l]};
        jobs.j[ji++] = {node_W3 + (size_t)l * HD * HD, 128, 128, oN3[l]};
    }
    dim3 cg((128 * 384 + 255) / 256, NJOBS);
    conv_w_kernel<<<cg, 256>>>(jobs);

    const int edge_blocks = NE / 128;           // 3125
    const int node_blocks = (NN + 127) / 128;   // 196
    const int scat_blocks = (int)(((size_t)NE * (HD / 4) + 255) / 256);
    const int nthr_blocks = (int)(((size_t)NN * HD + 255) / 256);

    // edge embedding: e = MLP(edge_attr)
    mma_mlp<0, 1><<<edge_blocks, 512, SMEM_DYN>>>(
        eattr, nullptr, oEmb1, oEmb2, oEmb3, 64,
        emb_b1, emb_b2, emb_b3, emb_g, emb_be, nullptr, eA, NE);

    const float* x_cur = x_in;
    float* e_cur = eA;
    for (int l = 0; l < 2; l++) {
        float* e_out = (l == 0) ? eB : out_e;
        float* x_out = (l == 0) ? xbuf : out_x;

        // e_new = MLP([x[dst] | x[src] | e]) + e
        mma_mlp<1, 6><<<edge_blocks, 512, SMEM_DYN>>>(
            x_cur, e_cur, oE1[l], oE2[l], oE3[l], 384,
            edge_b1 + l * HD, edge_b2 + l * HD, edge_b3 + l * HD,
            edge_g + l * HD, edge_be + l * HD, e_cur, e_out, NE);

        // agg = segment_sum(e_new, dst)
        zero_agg_kernel<<<nthr_blocks, 256>>>();
        scatter_kernel<<<scat_blocks, 256>>>(e_out);

        // x = MLP([x | agg]) + x
        mma_mlp<2, 4><<<node_blocks, 512, SMEM_DYN>>>(
            x_cur, agg, oN1[l], oN2[l], oN3[l], 256,
            node_b1 + l * HD, node_b2 + l * HD, node_b3 + l * HD,
            node_g + l * HD, node_be + l * HD, x_cur, x_out, NN);

        e_cur = e_out;
        x_cur = x_out;
    }
}

// round 10
// speedup vs baseline: 2.8550x; 1.0175x over previous
#include <cuda_runtime.h>
#include <cuda_fp16.h>
#include <cstdint>

#define NN 25000
#define NE 400000
#define HD 128
#define LN_EPS 1e-5f

// ================= device scratch =================
__device__ int   g_src[NE];
__device__ int   g_dst[NE];
__device__ int   g_is64;
__device__ float g_eA[(size_t)NE * HD];
__device__ float g_eB[(size_t)NE * HD];
__device__ float g_agg[(size_t)NN * HD];
__device__ float g_x[(size_t)NN * HD];

// fp16 hi/lo weight pools, [n=128][Kpad] row-major per matrix
#define POOL_ELEMS 335872
__device__ __align__(16) __half g_wh[POOL_ELEMS];
__device__ __align__(16) __half g_wl[POOL_ELEMS];

// ================= smem layout (dynamic, bytes) =================
#define LDT      144u
#define WB(i)    ((uint32_t)(i) * 36864u)            // 0, 36864
#define SL(i)    (73728u + (uint32_t)(i) * 36864u)   // 73728, 110592
#define SMEM_DYN 147456
// f32 LN staging overlays slot region: floats at byte 73728, stride 130 (66560 B)

// ================= helpers =================
__device__ __forceinline__ uint32_t smem_u32(const void* p) {
    uint32_t a;
    asm("{ .reg .u64 t; cvta.to.shared.u64 t, %1; cvt.u32.u64 %0, t; }"
        : "=r"(a) : "l"(p));
    return a;
}
__device__ __forceinline__ void ldsm4(uint32_t addr, uint32_t* r) {
    asm volatile("ldmatrix.sync.aligned.m8n8.x4.shared.b16 {%0,%1,%2,%3}, [%4];"
                 : "=r"(r[0]), "=r"(r[1]), "=r"(r[2]), "=r"(r[3]) : "r"(addr));
}
// NOTE: not volatile — pure register op, let the scheduler interleave.
__device__ __forceinline__ void mma16816(float* d, const uint32_t* a,
                                         uint32_t b0, uint32_t b1) {
    asm("mma.sync.aligned.m16n8k16.row.col.f32.f16.f16.f32 "
        "{%0,%1,%2,%3}, {%4,%5,%6,%7}, {%8,%9}, {%0,%1,%2,%3};"
        : "+f"(d[0]), "+f"(d[1]), "+f"(d[2]), "+f"(d[3])
        : "r"(a[0]), "r"(a[1]), "r"(a[2]), "r"(a[3]), "r"(b0), "r"(b1));
}
__device__ __forceinline__ void cp16(uint32_t dst, const void* src) {
    asm volatile("cp.async.cg.shared.global [%0], [%1], 16;"
                 :: "r"(dst), "l"(src));
}
#define CP_COMMIT() asm volatile("cp.async.commit_group;")
#define CP_WAIT0()  asm volatile("cp.async.wait_group 0;" ::: "memory")
__device__ __forceinline__ void pack_pair(float a, float b, uint32_t& hi, uint32_t& lo) {
    __half ha = __float2half_rn(a), hb = __float2half_rn(b);
    float ra = a - __half2float(ha);
    float rb = b - __half2float(hb);
    __half2 H = __halves2half2(ha, hb);
    __half2 L = __floats2half2_rn(ra, rb);
    hi = *reinterpret_cast<uint32_t*>(&H);
    lo = *reinterpret_cast<uint32_t*>(&L);
}
__device__ __forceinline__ float silu(float v) { return v / (1.f + __expf(-v)); }

// ================= index prep =================
__global__ void detect_kernel(const int* __restrict__ raw) {
    __shared__ int cnt;
    if (threadIdx.x == 0) cnt = 0;
    __syncthreads();
    int c = 0;
    for (int t = threadIdx.x; t < 1024; t += blockDim.x)
        if (raw[2 * t + 1] != 0) c++;
    atomicAdd(&cnt, c);
    __syncthreads();
    if (threadIdx.x == 0) g_is64 = (cnt < 16) ? 1 : 0;
}
__global__ void convert_kernel(const int* __restrict__ raw) {
    int i = blockIdx.x * blockDim.x + threadIdx.x;
    if (i >= NE) return;
    int s, d;
    if (g_is64) {
        const long long* p = (const long long*)raw;
        s = (int)p[i];
        d = (int)p[NE + i];
    } else {
        s = raw[i];
        d = raw[NE + i];
    }
    if ((unsigned)s >= NN) s = 0;
    if ((unsigned)d >= NN) d = 0;
    g_src[i] = s;
    g_dst[i] = d;
}

// ================= weight split prep =================
#define NJOBS 15
struct WJob { const float* src; int Ksrc; int Kpad; int dst; };
struct WJobs { WJob j[NJOBS]; };
__global__ void conv_w_kernel(WJobs jobs) {
    WJob jb = jobs.j[blockIdx.y];
    int idx = blockIdx.x * 256 + threadIdx.x;
    if (idx >= 128 * jb.Kpad) return;
    int n = idx / jb.Kpad, k = idx % jb.Kpad;
    float v = (k < jb.Ksrc) ? jb.src[(size_t)k * 128 + n] : 0.f;
    __half h = __float2half_rn(v);
    float r = v - __half2float(h);
    g_wh[(size_t)jb.dst + (size_t)n * jb.Kpad + k] = h;
    g_wl[(size_t)jb.dst + (size_t)n * jb.Kpad + k] = __float2half_rn(r);
}

// ================= A gather: load phase (regs) =================
// 512 threads: r = t>>2 (0..127), 16 k-halves per thread.
template <int MODE>
__device__ __forceinline__ void a_load(const float* __restrict__ in0,
                                       const float* __restrict__ in1,
                                       int chunk, int row0, int rows, int t,
                                       float4* v) {
    const int r = t >> 2;
    const int kh = (t & 3) << 4;          // 0,16,32,48
    const int gk = chunk * 64 + kh;
    const int row = row0 + r;
    const float* src = nullptr;
    if (MODE == 0) {
        if (kh == 0 && row < rows) src = in0 + (size_t)row * 16;
    } else if (MODE == 1) {
        if (row < rows) {
            int sect = gk >> 7;
            int coff = gk & 127;
            if (sect == 0)      src = in0 + (size_t)g_dst[row] * HD + coff;
            else if (sect == 1) src = in0 + (size_t)g_src[row] * HD + coff;
            else                src = in1 + (size_t)row * HD + coff;
        }
    } else {
        if (row < rows) {
            int sect = gk >> 7;
            int coff = gk & 127;
            src = (sect ? in1 : in0) + (size_t)row * HD + coff;
        }
    }
    v[0] = v[1] = v[2] = v[3] = make_float4(0.f, 0.f, 0.f, 0.f);
    if (src) {
        if (MODE == 0) {
            v[0] = *(const float4*)(src);
            v[1] = *(const float4*)(src + 4);
            v[2] = *(const float4*)(src + 8);
            v[3] = *(const float4*)(src + 12);
        } else {
            v[0] = *(const float4*)(src);
            v[1] = *(const float4*)(src + 4);
            v[2] = *(const float4*)(src + 8);
            v[3] = *(const float4*)(src + 12);
        }
    }
}

// A gather: pack + store phase
__device__ __forceinline__ void a_store(char* sm, uint32_t slot, int t, const float4* v) {
    const int r = t >> 2;
    const int kh = (t & 3) << 4;
    const uint32_t rbase = (uint32_t)r * LDT;
#pragma unroll
    for (int g = 0; g < 2; g++) {
        uint32_t h[4], l[4];
        pack_pair(v[2 * g].x,     v[2 * g].y,     h[0], l[0]);
        pack_pair(v[2 * g].z,     v[2 * g].w,     h[1], l[1]);
        pack_pair(v[2 * g + 1].x, v[2 * g + 1].y, h[2], l[2]);
        pack_pair(v[2 * g + 1].z, v[2 * g + 1].w, h[3], l[3]);
        uint32_t off = rbase + (uint32_t)(kh + g * 8) * 2u;
        *(uint4*)(sm + slot + off)          = make_uint4(h[0], h[1], h[2], h[3]);
        *(uint4*)(sm + slot + 18432u + off) = make_uint4(l[0], l[1], l[2], l[3]);
    }
}

// W tile via cp.async (512 threads); Kpad may be < 64 (emb layer 1)
__device__ __forceinline__ void load_w_async(uint32_t sb, uint32_t wb,
                                             int wofs, int kc, int Kpad, int t) {
    const int n = t >> 2;
    const int kh = (t & 3) << 4;
    if (kh >= Kpad) return;                // emb L1: Kpad=16, only kh==0 threads
    const __half* ph = g_wh + wofs + (size_t)n * Kpad + kc + kh;
    const __half* pl = g_wl + wofs + (size_t)n * Kpad + kc + kh;
    const uint32_t nb = (uint32_t)n * LDT;
#pragma unroll
    for (int g = 0; g < 2; g++) {
        uint32_t off = nb + (uint32_t)(kh + g * 8) * 2u;
        cp16(sb + wb + off, ph + g * 8);
        cp16(sb + wb + 18432u + off, pl + g * 8);
    }
}

// ================= warp MMA over one chunk; K16S k16-steps, pass-major =================
template <int K16S>
__device__ __forceinline__ void mma_chunk(uint32_t sb, uint32_t aB, uint32_t wB,
                                          float (&acc)[2][4][4], int m0, int n0, int lane) {
    const uint32_t aLo = aB + 18432u;
    const uint32_t wLo = wB + 18432u;
    const int rowA = m0 + (lane & 15);
    const int kselA = (lane >> 4) << 3;
    const uint32_t aB0 = (uint32_t)rowA * LDT;
    const uint32_t aB1 = aB0 + 16u * LDT;
    const int rowB = n0 + (lane & 7) + (((lane >> 4) & 1) << 3);
    const int kselB = ((lane >> 3) & 1) << 3;
#pragma unroll
    for (int ks = 0; ks < K16S; ks++) {
        const int k16 = ks * 16;
        uint32_t ah[2][4], al[2][4], bh[2][4], bl[2][4];
        uint32_t ak = (uint32_t)(k16 + kselA) * 2u;
        ldsm4(sb + aB + aB0 + ak, ah[0]);
        ldsm4(sb + aB + aB1 + ak, ah[1]);
        ldsm4(sb + aLo + aB0 + ak, al[0]);
        ldsm4(sb + aLo + aB1 + ak, al[1]);
        uint32_t bk = (uint32_t)(k16 + kselB) * 2u;
#pragma unroll
        for (int nb = 0; nb < 2; nb++) {
            uint32_t bb = (uint32_t)(rowB + nb * 16) * LDT;
            ldsm4(sb + wB + bb + bk, bh[nb]);
            ldsm4(sb + wLo + bb + bk, bl[nb]);
        }
        // pass 1: Ah x Wh (8 independent MMAs)
#pragma unroll
        for (int mi = 0; mi < 2; mi++)
#pragma unroll
            for (int nb = 0; nb < 2; nb++) {
                mma16816(acc[mi][nb * 2],     ah[mi], bh[nb][0], bh[nb][1]);
                mma16816(acc[mi][nb * 2 + 1], ah[mi], bh[nb][2], bh[nb][3]);
            }
        // pass 2: Al x Wh
#pragma unroll
        for (int mi = 0; mi < 2; mi++)
#pragma unroll
            for (int nb = 0; nb < 2; nb++) {
                mma16816(acc[mi][nb * 2],     al[mi], bh[nb][0], bh[nb][1]);
                mma16816(acc[mi][nb * 2 + 1], al[mi], bh[nb][2], bh[nb][3]);
            }
        // pass 3: Ah x Wl
#pragma unroll
        for (int mi = 0; mi < 2; mi++)
#pragma unroll
            for (int nb = 0; nb < 2; nb++) {
                mma16816(acc[mi][nb * 2],     ah[mi], bl[nb][0], bl[nb][1]);
                mma16816(acc[mi][nb * 2 + 1], ah[mi], bl[nb][2], bl[nb][3]);
            }
    }
}

__device__ __forceinline__ void zero_acc(float (&acc)[2][4][4]) {
#pragma unroll
    for (int mi = 0; mi < 2; mi++)
#pragma unroll
        for (int j = 0; j < 4; j++)
#pragma unroll
            for (int e = 0; e < 4; e++) acc[mi][j][e] = 0.f;
}

// ================= epilogues =================
__device__ __forceinline__ void epi_silu(char* sm, float (&acc)[2][4][4],
                                         const float* __restrict__ bias,
                                         int m0, int n0, int lane) {
    const int cq = (lane & 3) << 1;
    const int r0l = lane >> 2;
#pragma unroll
    for (int mi = 0; mi < 2; mi++)
#pragma unroll
        for (int j = 0; j < 4; j++) {
            int c = n0 + j * 8 + cq;
            float b0 = bias[c], b1 = bias[c + 1];
            uint32_t hiT = SL(c >> 6);
            int hc = c & 63;
#pragma unroll
            for (int h = 0; h < 2; h++) {
                float v0 = silu(acc[mi][j][2 * h] + b0);
                float v1 = silu(acc[mi][j][2 * h + 1] + b1);
                uint32_t hi, lo;
                pack_pair(v0, v1, hi, lo);
                int r = m0 + mi * 16 + r0l + 8 * h;
                uint32_t off = (uint32_t)r * LDT + (uint32_t)(hc * 2);
                *(uint32_t*)(sm + hiT + off)          = hi;
                *(uint32_t*)(sm + hiT + 18432u + off) = lo;
            }
        }
}

__device__ __forceinline__ void epi_ln(char* sm, float (&acc)[2][4][4],
                                       const float* __restrict__ bias,
                                       const float* __restrict__ gam,
                                       const float* __restrict__ bet,
                                       float (*sRed)[128][2],
                                       int m0, int n0, int wn, int lane) {
    const int cq = (lane & 3) << 1;
    const int r0l = lane >> 2;
    float s[2][2] = {{0.f, 0.f}, {0.f, 0.f}};
    float q[2][2] = {{0.f, 0.f}, {0.f, 0.f}};
#pragma unroll
    for (int mi = 0; mi < 2; mi++)
#pragma unroll
        for (int j = 0; j < 4; j++) {
            int c = n0 + j * 8 + cq;
            float b0 = bias[c], b1 = bias[c + 1];
#pragma unroll
            for (int h = 0; h < 2; h++) {
                float v0 = acc[mi][j][2 * h] + b0;
                float v1 = acc[mi][j][2 * h + 1] + b1;
                s[mi][h] += v0 + v1;
                q[mi][h] += v0 * v0 + v1 * v1;
            }
        }
#pragma unroll
    for (int o = 1; o <= 2; o <<= 1)
#pragma unroll
        for (int mi = 0; mi < 2; mi++)
#pragma unroll
            for (int h = 0; h < 2; h++) {
                s[mi][h] += __shfl_xor_sync(0xffffffffu, s[mi][h], o);
                q[mi][h] += __shfl_xor_sync(0xffffffffu, q[mi][h], o);
            }
    if ((lane & 3) == 0) {
#pragma unroll
        for (int mi = 0; mi < 2; mi++)
#pragma unroll
            for (int h = 0; h < 2; h++) {
                int r = m0 + mi * 16 + r0l + 8 * h;
                sRed[wn][r][0] = s[mi][h];
                sRed[wn][r][1] = q[mi][h];
            }
    }
    __syncthreads();
    float mu[2][2], rs[2][2];
#pragma unroll
    for (int mi = 0; mi < 2; mi++)
#pragma unroll
        for (int h = 0; h < 2; h++) {
            int r = m0 + mi * 16 + r0l + 8 * h;
            float S = sRed[0][r][0] + sRed[1][r][0] + sRed[2][r][0] + sRed[3][r][0];
            float Q = sRed[0][r][1] + sRed[1][r][1] + sRed[2][r][1] + sRed[3][r][1];
            float m = S * (1.f / HD);
            float var = Q * (1.f / HD) - m * m;
            mu[mi][h] = m;
            rs[mi][h] = rsqrtf(var + LN_EPS);
        }
    float* so = (float*)(sm + 73728u);  // stride 130 floats, 66560 B <= 73728
#pragma unroll
    for (int mi = 0; mi < 2; mi++)
#pragma unroll
        for (int j = 0; j < 4; j++) {
            int c = n0 + j * 8 + cq;
            float b0 = bias[c], b1 = bias[c + 1];
            float g0 = gam[c], g1 = gam[c + 1];
            float e0 = bet[c], e1 = bet[c + 1];
#pragma unroll
            for (int h = 0; h < 2; h++) {
                int r = m0 + mi * 16 + r0l + 8 * h;
                float v0 = acc[mi][j][2 * h] + b0;
                float v1 = acc[mi][j][2 * h + 1] + b1;
                so[r * 130 + c]     = (v0 - mu[mi][h]) * rs[mi][h] * g0 + e0;
                so[r * 130 + c + 1] = (v1 - mu[mi][h]) * rs[mi][h] * g1 + e1;
            }
        }
}

// ================= fused MLP kernel (512 threads, pipelined) =================
// K16S1: k16 steps per layer-1 chunk (4 normally, 1 for emb's K=16)
template <int MODE, int NCH, int K16S1>
__global__ __launch_bounds__(512, 1) void mma_mlp(
    const float* __restrict__ in0, const float* __restrict__ in1,
    int o1, int o2, int o3, int Kpad1,
    const float* __restrict__ b1, const float* __restrict__ b2,
    const float* __restrict__ b3, const float* __restrict__ gam,
    const float* __restrict__ bet,
    const float* __restrict__ resid, float* __restrict__ out, int rows) {
    extern __shared__ char sm[];
    __shared__ float sRed[4][128][2];
    const int t = threadIdx.x;
    const uint32_t sb = smem_u32(sm);
    const int lane = t & 31, w = t >> 5;
    const int m0 = (w & 3) * 32, n0 = (w >> 2) * 32, wn = w >> 2;
    const int row0 = blockIdx.x * 128;
    float acc[2][4][4];
    float4 v[4];

    // ---- layer 1: pipelined chunks, one sync each ----
    zero_acc(acc);
    for (int c = 0; c < NCH; c++) {
        __syncthreads();
        a_load<MODE>(in0, in1, c, row0, rows, t, v);
        load_w_async(sb, WB(c & 1), o1, c * 64, Kpad1, t);
        CP_COMMIT();
        if (c > 0) mma_chunk<K16S1>(sb, SL((c - 1) & 1), WB((c - 1) & 1), acc, m0, n0, lane);
        CP_WAIT0();
        a_store((char*)sm, SL(c & 1), t, v);
    }
    __syncthreads();
    mma_chunk<K16S1>(sb, SL((NCH - 1) & 1), WB((NCH - 1) & 1), acc, m0, n0, lane);
    __syncthreads();

    // ---- layer 2 ----
    load_w_async(sb, WB(0), o2, 0, 128, t);
    load_w_async(sb, WB(1), o2, 64, 128, t);
    CP_COMMIT();
    epi_silu((char*)sm, acc, b1, m0, n0, lane);
    zero_acc(acc);
    CP_WAIT0();
    __syncthreads();
    mma_chunk<4>(sb, SL(0), WB(0), acc, m0, n0, lane);
    mma_chunk<4>(sb, SL(1), WB(1), acc, m0, n0, lane);
    __syncthreads();

    // ---- layer 3 ----
    load_w_async(sb, WB(0), o3, 0, 128, t);
    load_w_async(sb, WB(1), o3, 64, 128, t);
    CP_COMMIT();
    epi_silu((char*)sm, acc, b2, m0, n0, lane);
    zero_acc(acc);
    CP_WAIT0();
    __syncthreads();
    mma_chunk<4>(sb, SL(0), WB(0), acc, m0, n0, lane);
    mma_chunk<4>(sb, SL(1), WB(1), acc, m0, n0, lane);
    __syncthreads();
    epi_ln((char*)sm, acc, b3, gam, bet, sRed, m0, n0, wn, lane);
    __syncthreads();

    // ---- residual + coalesced store ----
    const float* so = (const float*)(sm + 73728u);
    const int col = t & 127;
    for (int r = (t >> 7); r < 128; r += 4) {
        int row = row0 + r;
        if (row < rows) {
            float y = so[r * 130 + col];
            if (MODE != 0) y += resid[(size_t)row * HD + col];
            out[(size_t)row * HD + col] = y;
        }
    }
}

// ================= aggregation =================
__global__ void zero_agg_kernel() {
    size_t i = (size_t)blockIdx.x * blockDim.x + threadIdx.x;
    if (i < (size_t)NN * HD) g_agg[i] = 0.f;
}
// vectorized scatter: one red.v4 per 4 floats
__global__ void scatter_kernel(const float* __restrict__ e) {
    size_t i = (size_t)blockIdx.x * blockDim.x + threadIdx.x;
    if (i >= (size_t)NE * (HD / 4)) return;
    int edge = (int)(i >> 5);
    int c = (int)(i & 31) << 2;
    float4 val = *(const float4*)(e + (size_t)edge * HD + c);
    float* p = g_agg + (size_t)g_dst[edge] * HD + c;
    asm volatile("red.global.add.v4.f32 [%0], {%1, %2, %3, %4};"
                 :: "l"(p), "f"(val.x), "f"(val.y), "f"(val.z), "f"(val.w)
                 : "memory");
}

// ================= launch =================
extern "C" void kernel_launch(void* const* d_in, const int* in_sizes, int n_in,
                              void* d_out, int out_size) {
    const float* x_in    = (const float*)d_in[0];
    const int*   eidx    = (const int*)d_in[1];
    const float* eattr   = (const float*)d_in[2];
    const float* emb_W1  = (const float*)d_in[3];
    const float* emb_b1  = (const float*)d_in[4];
    const float* emb_W2  = (const float*)d_in[5];
    const float* emb_b2  = (const float*)d_in[6];
    const float* emb_W3  = (const float*)d_in[7];
    const float* emb_b3  = (const float*)d_in[8];
    const float* emb_g   = (const float*)d_in[9];
    const float* emb_be  = (const float*)d_in[10];
    const float* edge_W1 = (const float*)d_in[11];
    const float* edge_b1 = (const float*)d_in[12];
    const float* edge_W2 = (const float*)d_in[13];
    const float* edge_b2 = (const float*)d_in[14];
    const float* edge_W3 = (const float*)d_in[15];
    const float* edge_b3 = (const float*)d_in[16];
    const float* edge_g  = (const float*)d_in[17];
    const float* edge_be = (const float*)d_in[18];
    const float* node_W1 = (const float*)d_in[19];
    const float* node_b1 = (const float*)d_in[20];
    const float* node_W2 = (const float*)d_in[21];
    const float* node_b2 = (const float*)d_in[22];
    const float* node_W3 = (const float*)d_in[23];
    const float* node_b3 = (const float*)d_in[24];
    const float* node_g  = (const float*)d_in[25];
    const float* node_be = (const float*)d_in[26];

    float* out_x = (float*)d_out;
    float* out_e = (float*)d_out + (size_t)NN * HD;

    float *eA, *eB, *agg, *xbuf;
    cudaGetSymbolAddress((void**)&eA, g_eA);
    cudaGetSymbolAddress((void**)&eB, g_eB);
    cudaGetSymbolAddress((void**)&agg, g_agg);
    cudaGetSymbolAddress((void**)&xbuf, g_x);

    cudaFuncSetAttribute((const void*)mma_mlp<0, 1, 1>, cudaFuncAttributeMaxDynamicSharedMemorySize, SMEM_DYN);
    cudaFuncSetAttribute((const void*)mma_mlp<1, 6, 4>, cudaFuncAttributeMaxDynamicSharedMemorySize, SMEM_DYN);
    cudaFuncSetAttribute((const void*)mma_mlp<2, 4, 4>, cudaFuncAttributeMaxDynamicSharedMemorySize, SMEM_DYN);

    // index prep (clamped)
    detect_kernel<<<1, 256>>>(eidx);
    convert_kernel<<<(NE + 255) / 256, 256>>>(eidx);

    // pool offsets (elements)
    const int oEmb1 = 0, oEmb2 = 8192, oEmb3 = 24576;  // emb1 uses 128*16=2048
    int oE1[2], oE2[2], oE3[2], oN1[2], oN2[2], oN3[2];
    int base = 40960;
    for (int l = 0; l < 2; l++) {
        oE1[l] = base;
        oE2[l] = base + 49152;
        oE3[l] = base + 65536;
        oN1[l] = base + 81920;
        oN2[l] = base + 114688;
        oN3[l] = base + 131072;
        base += 147456;
    }

    WJobs jobs;
    int ji = 0;
    jobs.j[ji++] = {emb_W1, 16, 16, oEmb1};   // exact K=16, no padding
    jobs.j[ji++] = {emb_W2, 128, 128, oEmb2};
    jobs.j[ji++] = {emb_W3, 128, 128, oEmb3};
    for (int l = 0; l < 2; l++) {
        jobs.j[ji++] = {edge_W1 + (size_t)l * 3 * HD * HD, 384, 384, oE1[l]};
        jobs.j[ji++] = {edge_W2 + (size_t)l * HD * HD, 128, 128, oE2[l]};
        jobs.j[ji++] = {edge_W3 + (size_t)l * HD * HD, 128, 128, oE3[l]};
        jobs.j[ji++] = {node_W1 + (size_t)l * 2 * HD * HD, 256, 256, oN1[l]};
        jobs.j[ji++] = {node_W2 + (size_t)l * HD * HD, 128, 128, oN2[l]};
        jobs.j[ji++] = {node_W3 + (size_t)l * HD * HD, 128, 128, oN3[l]};
    }
    dim3 cg((128 * 384 + 255) / 256, NJOBS);
    conv_w_kernel<<<cg, 256>>>(jobs);

    const int edge_blocks = NE / 128;           // 3125
    const int node_blocks = (NN + 127) / 128;   // 196
    const int scat_blocks = (int)(((size_t)NE * (HD / 4) + 255) / 256);
    const int nthr_blocks = (int)(((size_t)NN * HD + 255) / 256);

    // edge embedding: e = MLP(edge_attr)  (layer 1 runs exactly K=16)
    mma_mlp<0, 1, 1><<<edge_blocks, 512, SMEM_DYN>>>(
        eattr, nullptr, oEmb1, oEmb2, oEmb3, 16,
        emb_b1, emb_b2, emb_b3, emb_g, emb_be, nullptr, eA, NE);

    const float* x_cur = x_in;
    float* e_cur = eA;
    for (int l = 0; l < 2; l++) {
        float* e_out = (l == 0) ? eB : out_e;
        float* x_out = (l == 0) ? xbuf : out_x;

        // e_new = MLP([x[dst] | x[src] | e]) + e
        mma_mlp<1, 6, 4><<<edge_blocks, 512, SMEM_DYN>>>(
            x_cur, e_cur, oE1[l], oE2[l], oE3[l], 384,
            edge_b1 + l * HD, edge_b2 + l * HD, edge_b3 + l * HD,
            edge_g + l * HD, edge_be + l * HD, e_cur, e_out, NE);

        // agg = segment_sum(e_new, dst)
        zero_agg_kernel<<<nthr_blocks, 256>>>();
        scatter_kernel<<<scat_blocks, 256>>>(e_out);

        // x = MLP([x | agg]) + x
        mma_mlp<2, 4, 4><<<node_blocks, 512, SMEM_DYN>>>(
            x_cur, agg, oN1[l], oN2[l], oN3[l], 256,
            node_b1 + l * HD, node_b2 + l * HD, node_b3 + l * HD,
            node_g + l * HD, node_be + l * HD, x_cur, x_out, NN);

        e_cur = e_out;
        x_cur = x_out;
    }
}